// round 1
// baseline (speedup 1.0000x reference)
#include <cuda_runtime.h>
#include <cuda_bf16.h>
#include <math.h>

// Problem constants
#define BATCH 2
#define SEQ   2048
#define DM    1024
#define NH    16
#define HD    64
#define FF    4096
#define MROWS (BATCH * SEQ)   // 4096

// ---------------- scratch (static device globals; no allocations) ----------
__device__ float g_xn [MROWS * DM];    // rmsnorm(x)
__device__ float g_xr [MROWS * DM];    // rope(rmsnorm(x))
__device__ float g_qk [MROWS * 2 * DM];// q (cols 0..1023) and k (cols 1024..2047)
__device__ float g_v  [MROWS * DM];
__device__ float g_ctx[MROWS * DM];    // attention context in [b,t,h,d] layout
__device__ float g_y  [MROWS * DM];    // attention output (pre-FFN residual)
__device__ float g_yn [MROWS * DM];    // rmsnorm(y)
__device__ float g_h  [MROWS * FF];    // silu(yn @ w1^T + b1)

// ---------------- RMSNorm (+ optional interleaved RoPE) --------------------
// one block per row; 256 threads; 4 floats/thread
__global__ void __launch_bounds__(256) rms_rope_kernel(
    const float* __restrict__ x, const float* __restrict__ scale,
    float* __restrict__ xn, float* __restrict__ xr)
{
    const int row = blockIdx.x;
    const int tid = threadIdx.x;
    __shared__ float red[8];
    __shared__ float th[32];

    if (xr != nullptr && tid < 32) {
        // theta_p = 10000^(-2p/64), computed in double for accuracy
        th[tid] = (float)exp(-((double)(2 * tid) / 64.0) * 9.210340371976184);
    }

    float4 v = *(const float4*)(x + (size_t)row * DM + tid * 4);
    float ss = v.x * v.x + v.y * v.y + v.z * v.z + v.w * v.w;
    #pragma unroll
    for (int o = 16; o > 0; o >>= 1) ss += __shfl_xor_sync(0xffffffffu, ss, o);
    if ((tid & 31) == 0) red[tid >> 5] = ss;
    __syncthreads();
    float tot = 0.f;
    #pragma unroll
    for (int i = 0; i < 8; i++) tot += red[i];
    const float r = rsqrtf(tot * (1.0f / (float)DM) + 1e-6f);

    float4 sc = *(const float4*)(scale + tid * 4);
    float4 n;
    n.x = v.x * r * sc.x;
    n.y = v.y * r * sc.y;
    n.z = v.z * r * sc.z;
    n.w = v.w * r * sc.w;
    *(float4*)(xn + (size_t)row * DM + tid * 4) = n;

    if (xr != nullptr) {
        const int t = row & (SEQ - 1);          // row = b*SEQ + t
        const int c = (tid * 4) & (HD - 1);     // position within head
        const int p = c >> 1;                   // pair index for (n.x,n.y); p+1 for (n.z,n.w)
        float a0 = (float)t * th[p];
        float a1 = (float)t * th[p + 1];
        float s0, c0, s1, c1;
        sincosf(a0, &s0, &c0);
        sincosf(a1, &s1, &c1);
        float4 o;
        o.x = n.x * c0 - n.y * s0;
        o.y = n.y * c0 + n.x * s0;
        o.z = n.z * c1 - n.w * s1;
        o.w = n.w * c1 + n.z * s1;
        *(float4*)(xr + (size_t)row * DM + tid * 4) = o;
    }
}

// ---------------- SGEMM: C[M,N] = A[M,K] @ W[N,K]^T + bias (+silu)(+res) ---
// 128x128 tile, BK=16, 256 threads, 8x8 microtile per thread
#define BM 128
#define BN 128
#define BKT 16

template <int ACT, int RES>
__global__ void __launch_bounds__(256) gemm_nt_kernel(
    const float* __restrict__ A, int lda,
    const float* __restrict__ W,            // [N,K] row-major
    const float* __restrict__ bias,
    const float* __restrict__ resid, int ldr,
    float* __restrict__ C, int ldc,
    int M, int N, int K)
{
    __shared__ float As[BKT][BM];
    __shared__ float Bs[BKT][BN];

    const int tid = threadIdx.x;
    const int tx = tid & 15;       // N direction
    const int ty = tid >> 4;       // M direction
    const int m0 = blockIdx.y * BM;
    const int n0 = blockIdx.x * BN;

    const int lrow = tid >> 1;         // 0..127
    const int lcol = (tid & 1) * 8;    // 0 or 8
    const float* Ag = A + (size_t)(m0 + lrow) * lda + lcol;
    const float* Wg = W + (size_t)(n0 + lrow) * K + lcol;

    float acc[8][8];
    #pragma unroll
    for (int i = 0; i < 8; i++)
        #pragma unroll
        for (int j = 0; j < 8; j++) acc[i][j] = 0.f;

    for (int k0 = 0; k0 < K; k0 += BKT) {
        float4 a0 = *(const float4*)(Ag + k0);
        float4 a1 = *(const float4*)(Ag + k0 + 4);
        float4 b0 = *(const float4*)(Wg + k0);
        float4 b1 = *(const float4*)(Wg + k0 + 4);
        __syncthreads();
        As[lcol + 0][lrow] = a0.x; As[lcol + 1][lrow] = a0.y;
        As[lcol + 2][lrow] = a0.z; As[lcol + 3][lrow] = a0.w;
        As[lcol + 4][lrow] = a1.x; As[lcol + 5][lrow] = a1.y;
        As[lcol + 6][lrow] = a1.z; As[lcol + 7][lrow] = a1.w;
        Bs[lcol + 0][lrow] = b0.x; Bs[lcol + 1][lrow] = b0.y;
        Bs[lcol + 2][lrow] = b0.z; Bs[lcol + 3][lrow] = b0.w;
        Bs[lcol + 4][lrow] = b1.x; Bs[lcol + 5][lrow] = b1.y;
        Bs[lcol + 6][lrow] = b1.z; Bs[lcol + 7][lrow] = b1.w;
        __syncthreads();

        #pragma unroll
        for (int kk = 0; kk < BKT; kk++) {
            float4 ra0 = *(const float4*)&As[kk][ty * 8];
            float4 ra1 = *(const float4*)&As[kk][ty * 8 + 4];
            float4 rb0 = *(const float4*)&Bs[kk][tx * 8];
            float4 rb1 = *(const float4*)&Bs[kk][tx * 8 + 4];
            float ar[8] = {ra0.x, ra0.y, ra0.z, ra0.w, ra1.x, ra1.y, ra1.z, ra1.w};
            float br[8] = {rb0.x, rb0.y, rb0.z, rb0.w, rb1.x, rb1.y, rb1.z, rb1.w};
            #pragma unroll
            for (int i = 0; i < 8; i++)
                #pragma unroll
                for (int j = 0; j < 8; j++)
                    acc[i][j] = fmaf(ar[i], br[j], acc[i][j]);
        }
    }

    #pragma unroll
    for (int i = 0; i < 8; i++) {
        const int m = m0 + ty * 8 + i;
        #pragma unroll
        for (int j = 0; j < 8; j++) {
            const int n = n0 + tx * 8 + j;
            float v = acc[i][j] + bias[n];
            if (ACT == 1) v = v / (1.0f + __expf(-v));   // silu
            if (RES == 1) v += resid[(size_t)m * ldr + n];
            C[(size_t)m * ldc + n] = v;
        }
    }
}

// ---------------- causal flash attention (fp32, per-thread query) ----------
// grid (SEQ/128, NH, BATCH), 128 threads; thread owns one query row.
#define SKT 32
__global__ void __launch_bounds__(128) flash_attn_kernel(
    const float* __restrict__ qk, const float* __restrict__ v,
    float* __restrict__ ctx)
{
    const int t = blockIdx.x * 128 + threadIdx.x;
    const int h = blockIdx.y;
    const int b = blockIdx.z;
    const int row = b * SEQ + t;

    float4 q[16];
    const float4* qp = (const float4*)(qk + (size_t)row * (2 * DM) + h * HD);
    #pragma unroll
    for (int i = 0; i < 16; i++) q[i] = qp[i];

    float4 o[16];
    #pragma unroll
    for (int i = 0; i < 16; i++) o[i] = make_float4(0.f, 0.f, 0.f, 0.f);
    float m = -1e30f, l = 0.f;

    __shared__ float4 Ks[SKT][16];
    __shared__ float4 Vs[SKT][16];

    const int kend = blockIdx.x * 128 + 127;
    for (int k0 = 0; k0 <= kend; k0 += SKT) {
        __syncthreads();
        #pragma unroll
        for (int i = threadIdx.x; i < SKT * 16; i += 128) {
            const int r = i >> 4, c = i & 15;
            const int krow = b * SEQ + k0 + r;
            Ks[r][c] = *(const float4*)(qk + (size_t)krow * (2 * DM) + DM + h * HD + c * 4);
            Vs[r][c] = *(const float4*)(v + (size_t)krow * DM + h * HD + c * 4);
        }
        __syncthreads();
        if (k0 > t) continue;

        float s[SKT];
        float tmax = -1e30f;
        #pragma unroll
        for (int kk = 0; kk < SKT; kk++) {
            float acc = 0.f;
            #pragma unroll
            for (int c = 0; c < 16; c++) {
                float4 kv = Ks[kk][c];
                acc = fmaf(q[c].x, kv.x, acc);
                acc = fmaf(q[c].y, kv.y, acc);
                acc = fmaf(q[c].z, kv.z, acc);
                acc = fmaf(q[c].w, kv.w, acc);
            }
            s[kk] = (k0 + kk <= t) ? acc * 0.125f : -1e30f;
            tmax = fmaxf(tmax, s[kk]);
        }
        const float mnew = fmaxf(m, tmax);
        const float corr = __expf(m - mnew);
        l *= corr;
        #pragma unroll
        for (int c = 0; c < 16; c++) {
            o[c].x *= corr; o[c].y *= corr; o[c].z *= corr; o[c].w *= corr;
        }
        #pragma unroll
        for (int kk = 0; kk < SKT; kk++) {
            const float p = __expf(s[kk] - mnew);
            l += p;
            #pragma unroll
            for (int c = 0; c < 16; c++) {
                float4 vv = Vs[kk][c];
                o[c].x = fmaf(p, vv.x, o[c].x);
                o[c].y = fmaf(p, vv.y, o[c].y);
                o[c].z = fmaf(p, vv.z, o[c].z);
                o[c].w = fmaf(p, vv.w, o[c].w);
            }
        }
        m = mnew;
    }

    const float inv = 1.0f / l;
    float4* op = (float4*)(ctx + (size_t)row * DM + h * HD);
    #pragma unroll
    for (int c = 0; c < 16; c++) {
        float4 ov = o[c];
        ov.x *= inv; ov.y *= inv; ov.z *= inv; ov.w *= inv;
        op[c] = ov;
    }
}

// ---------------- launch ---------------------------------------------------
extern "C" void kernel_launch(void* const* d_in, const int* in_sizes, int n_in,
                              void* d_out, int out_size)
{
    const float* x         = (const float*)d_in[0];
    const float* rms_scale = (const float*)d_in[1];
    const float* in_proj_w = (const float*)d_in[2];
    const float* in_proj_b = (const float*)d_in[3];
    const float* out_proj_w= (const float*)d_in[4];
    const float* out_proj_b= (const float*)d_in[5];
    const float* w1        = (const float*)d_in[6];
    const float* b1        = (const float*)d_in[7];
    const float* w2        = (const float*)d_in[8];
    const float* b2        = (const float*)d_in[9];
    float* out = (float*)d_out;

    static float *p_xn = nullptr, *p_xr, *p_qk, *p_v, *p_ctx, *p_y, *p_yn, *p_h;
    if (!p_xn) {
        cudaGetSymbolAddress((void**)&p_xn,  g_xn);
        cudaGetSymbolAddress((void**)&p_xr,  g_xr);
        cudaGetSymbolAddress((void**)&p_qk,  g_qk);
        cudaGetSymbolAddress((void**)&p_v,   g_v);
        cudaGetSymbolAddress((void**)&p_ctx, g_ctx);
        cudaGetSymbolAddress((void**)&p_y,   g_y);
        cudaGetSymbolAddress((void**)&p_yn,  g_yn);
        cudaGetSymbolAddress((void**)&p_h,   g_h);
    }

    // 1) xn = rmsnorm(x); xr = rope(xn)
    rms_rope_kernel<<<MROWS, 256>>>(x, rms_scale, p_xn, p_xr);

    // 2) [q|k] = xr @ [Wq;Wk]^T + [bq;bk]   (N = 2048)
    gemm_nt_kernel<0, 0><<<dim3(2 * DM / BN, MROWS / BM), 256>>>(
        p_xr, DM, in_proj_w, in_proj_b, nullptr, 0,
        p_qk, 2 * DM, MROWS, 2 * DM, DM);

    // 3) v = xn @ Wv^T + bv
    gemm_nt_kernel<0, 0><<<dim3(DM / BN, MROWS / BM), 256>>>(
        p_xn, DM, in_proj_w + (size_t)(2 * DM) * DM, in_proj_b + 2 * DM, nullptr, 0,
        p_v, DM, MROWS, DM, DM);

    // 4) causal attention -> ctx in [b,t,h,d] layout
    flash_attn_kernel<<<dim3(SEQ / 128, NH, BATCH), 128>>>(p_qk, p_v, p_ctx);

    // 5) y = ctx @ out_proj_w^T + out_proj_b
    gemm_nt_kernel<0, 0><<<dim3(DM / BN, MROWS / BM), 256>>>(
        p_ctx, DM, out_proj_w, out_proj_b, nullptr, 0,
        p_y, DM, MROWS, DM, DM);

    // 6) yn = rmsnorm(y)
    rms_rope_kernel<<<MROWS, 256>>>(p_y, rms_scale, p_yn, nullptr);

    // 7) h = silu(yn @ w1^T + b1)
    gemm_nt_kernel<1, 0><<<dim3(FF / BN, MROWS / BM), 256>>>(
        p_yn, DM, w1, b1, nullptr, 0,
        p_h, FF, MROWS, FF, DM);

    // 8) out = y + (h @ w2^T + b2)
    gemm_nt_kernel<0, 1><<<dim3(DM / BN, MROWS / BM), 256>>>(
        p_h, FF, w2, b2, p_y, DM,
        out, DM, MROWS, DM, FF);
}

// round 3
// speedup vs baseline: 1.6861x; 1.6861x over previous
#include <cuda_runtime.h>
#include <cuda_bf16.h>
#include <cstdint>
#include <math.h>

// Problem constants
#define BATCH 2
#define SEQ   2048
#define DM    1024
#define NH    16
#define HD    64
#define FF    4096
#define MROWS (BATCH * SEQ)   // 4096

// GEMM tiling: CTA 128x128, K-chunk 64 (SW128 tiles of 128 rows x 64 bf16)
#define TILE_ELEMS 8192                 // 128*64
#define STAGE_BYTES 65536               // 4 x 16KB buffers (Ahi,Alo,Bhi,Blo)
#define GEMM_SMEM   (2 * STAGE_BYTES + 256)

// ---------------- scratch (static device globals; no allocations) ----------
__device__ float g_qk [MROWS * 2 * DM];
__device__ float g_v  [MROWS * DM];
__device__ float g_y  [MROWS * DM];

// bf16 hi/lo tiled operands (SW128-swizzled 128x64 tiles)
__device__ __nv_bfloat16 t_xr_hi [MROWS * DM],  t_xr_lo [MROWS * DM];
__device__ __nv_bfloat16 t_xn_hi [MROWS * DM],  t_xn_lo [MROWS * DM];
__device__ __nv_bfloat16 t_ctx_hi[MROWS * DM],  t_ctx_lo[MROWS * DM];
__device__ __nv_bfloat16 t_yn_hi [MROWS * DM],  t_yn_lo [MROWS * DM];
__device__ __nv_bfloat16 t_h_hi  [MROWS * FF],  t_h_lo  [MROWS * FF];
__device__ __nv_bfloat16 t_wqk_hi[2048 * DM],   t_wqk_lo[2048 * DM];
__device__ __nv_bfloat16 t_wv_hi [DM * DM],     t_wv_lo [DM * DM];
__device__ __nv_bfloat16 t_wo_hi [DM * DM],     t_wo_lo [DM * DM];
__device__ __nv_bfloat16 t_w1_hi [FF * DM],     t_w1_lo [FF * DM];
__device__ __nv_bfloat16 t_w2_hi [DM * FF],     t_w2_lo [DM * FF];

// ---------------- helpers ---------------------------------------------------
__device__ __forceinline__ uint32_t sw128(uint32_t o) { return o ^ ((o >> 3) & 0x70); }

__device__ __forceinline__ void split_store(__nv_bfloat16* hi, __nv_bfloat16* lo,
                                            size_t idx, float v)
{
    __nv_bfloat16 h = __float2bfloat16(v);
    hi[idx] = h;
    lo[idx] = __float2bfloat16(v - __bfloat162float(h));
}

// fast exp on the FMA pipe
__device__ __forceinline__ float fexp(float x)
{
    x = fminf(fmaxf(x, -87.f), 87.f);
    float y = x * 1.4426950408889634f;
    float r = rintf(y);
    float f = y - r;
    float p = 1.33336498e-3f;
    p = fmaf(p, f, 9.61793571e-3f);
    p = fmaf(p, f, 5.55043442e-2f);
    p = fmaf(p, f, 2.40226507e-1f);
    p = fmaf(p, f, 6.93147182e-1f);
    p = fmaf(p, f, 1.0f);
    return p * __int_as_float(((int)r + 127) << 23);
}

__device__ __forceinline__ uint32_t smem_u32(const void* p)
{
    uint32_t a;
    asm("{ .reg .u64 t; cvta.to.shared.u64 t, %1; cvt.u32.u64 %0, t; }" : "=r"(a) : "l"(p));
    return a;
}

__device__ __forceinline__ void cp16(uint32_t s, const void* g)
{
    asm volatile("cp.async.cg.shared.global [%0], [%1], 16;" :: "r"(s), "l"(g));
}

__device__ __forceinline__ void ldsm4(uint32_t* r, uint32_t addr)
{
    asm volatile("ldmatrix.sync.aligned.m8n8.x4.shared.b16 {%0,%1,%2,%3}, [%4];"
                 : "=r"(r[0]), "=r"(r[1]), "=r"(r[2]), "=r"(r[3]) : "r"(addr));
}

__device__ __forceinline__ void mma_bf16(float* d, const uint32_t* a, const uint32_t* b)
{
    asm volatile(
        "mma.sync.aligned.m16n8k16.row.col.f32.bf16.bf16.f32 "
        "{%0,%1,%2,%3}, {%4,%5,%6,%7}, {%8,%9}, {%0,%1,%2,%3};"
        : "+f"(d[0]), "+f"(d[1]), "+f"(d[2]), "+f"(d[3])
        : "r"(a[0]), "r"(a[1]), "r"(a[2]), "r"(a[3]), "r"(b[0]), "r"(b[1]));
}

// ---------------- RMSNorm (+ optional RoPE); outputs tiled bf16 hi/lo -------
__global__ void __launch_bounds__(256) rms_rope_kernel(
    const float* __restrict__ x, const float* __restrict__ scale,
    __nv_bfloat16* __restrict__ n_hi, __nv_bfloat16* __restrict__ n_lo,
    __nv_bfloat16* __restrict__ r_hi, __nv_bfloat16* __restrict__ r_lo)
{
    const int row = blockIdx.x;
    const int tid = threadIdx.x;
    __shared__ float red[8];
    __shared__ float th[32];

    if (tid < 32)
        th[tid] = (float)exp(-((double)(2 * tid) / 64.0) * 9.210340371976184);

    float4 v = *(const float4*)(x + (size_t)row * DM + tid * 4);
    float ss = v.x * v.x + v.y * v.y + v.z * v.z + v.w * v.w;
    #pragma unroll
    for (int o = 16; o > 0; o >>= 1) ss += __shfl_xor_sync(0xffffffffu, ss, o);
    if ((tid & 31) == 0) red[tid >> 5] = ss;
    __syncthreads();
    float tot = 0.f;
    #pragma unroll
    for (int i = 0; i < 8; i++) tot += red[i];
    const float r = rsqrtf(tot * (1.0f / (float)DM) + 1e-6f);

    float4 sc = *(const float4*)(scale + tid * 4);
    float4 n;
    n.x = v.x * r * sc.x;
    n.y = v.y * r * sc.y;
    n.z = v.z * r * sc.z;
    n.w = v.w * r * sc.w;

    const int mt = row >> 7, rr = row & 127;
    const int c0 = tid * 4;
    const int kc = c0 >> 6, kk = c0 & 63;
    const size_t base = ((size_t)mt * (DM / 64) + kc) * TILE_ELEMS;
    const uint32_t off = sw128(rr * 128 + kk * 2) >> 1;
    split_store(n_hi, n_lo, base + off + 0, n.x);
    split_store(n_hi, n_lo, base + off + 1, n.y);
    split_store(n_hi, n_lo, base + off + 2, n.z);
    split_store(n_hi, n_lo, base + off + 3, n.w);

    if (r_hi != nullptr) {
        const int t = row & (SEQ - 1);
        const int c = c0 & (HD - 1);
        const int p = c >> 1;
        float a0 = (float)t * th[p];
        float a1 = (float)t * th[p + 1];
        float s0, co0, s1, co1;
        sincosf(a0, &s0, &co0);
        sincosf(a1, &s1, &co1);
        float4 o;
        o.x = n.x * co0 - n.y * s0;
        o.y = n.y * co0 + n.x * s0;
        o.z = n.z * co1 - n.w * s1;
        o.w = n.w * co1 + n.z * s1;
        split_store(r_hi, r_lo, base + off + 0, o.x);
        split_store(r_hi, r_lo, base + off + 1, o.y);
        split_store(r_hi, r_lo, base + off + 2, o.z);
        split_store(r_hi, r_lo, base + off + 3, o.w);
    }
}

// ---------------- fp32 [N,K] -> tiled bf16 hi/lo (128-row tiles) ------------
__global__ void __launch_bounds__(256) conv_tiled_kernel(
    const float* __restrict__ in, int K,
    __nv_bfloat16* __restrict__ hi, __nv_bfloat16* __restrict__ lo)
{
    const int kc = blockIdx.x;
    const int rt = blockIdx.y;
    const int NCk = gridDim.x;
    const size_t base = ((size_t)rt * NCk + kc) * (size_t)TILE_ELEMS;
    for (int idx = threadIdx.x; idx < TILE_ELEMS; idx += 256) {
        const int r = idx >> 6, k = idx & 63;
        float v = in[(size_t)(rt * 128 + r) * K + kc * 64 + k];
        const uint32_t off = sw128(r * 128 + k * 2) >> 1;
        split_store(hi, lo, base + off, v);
    }
}

// ---------------- mma.sync bf16x3 GEMM: C = A @ B^T + bias (+silu)(+res) ----
// CTA 128x128, 256 threads = 8 warps (4M x 2N), warp tile 32x64
template <int ACT, int RES, int OUTT>
__global__ void __launch_bounds__(256) gemm_mma(
    const __nv_bfloat16* __restrict__ Ahi, const __nv_bfloat16* __restrict__ Alo,
    const __nv_bfloat16* __restrict__ Bhi, const __nv_bfloat16* __restrict__ Blo,
    const float* __restrict__ bias, const float* __restrict__ resid,
    float* __restrict__ C, __nv_bfloat16* __restrict__ Ohi, __nv_bfloat16* __restrict__ Olo,
    int N, int K)
{
    extern __shared__ char smem[];
    const uint32_t sbase = (smem_u32(smem) + 127) & ~127u;

    const int tid = threadIdx.x;
    const int lane = tid & 31, wid = tid >> 5;
    const int wm = wid >> 1, wn = wid & 1;
    const int NC = K >> 6;
    const int mt = blockIdx.y, nt = blockIdx.x;

    // per-lane ldmatrix address precompute (SW128-swizzled)
    const uint32_t xr = (uint32_t)((lane & 7) << 4);
    uint32_t aRow[2];
    #pragma unroll
    for (int mi = 0; mi < 2; mi++)
        aRow[mi] = (uint32_t)((wm * 32 + mi * 16 + (lane & 15)) * 128);
    const uint32_t kA = (uint32_t)((lane >> 4) * 16);

    const int nb = wn * 64 + ((lane >> 4) << 3) + (lane & 7);
    uint32_t bRow[4];
    #pragma unroll
    for (int np = 0; np < 4; np++)
        bRow[np] = (uint32_t)((nb + np * 16) * 128);
    const uint32_t kB = (uint32_t)(((lane >> 3) & 1) * 16);

    float acc[2][8][4];
    #pragma unroll
    for (int mi = 0; mi < 2; mi++)
        #pragma unroll
        for (int nj = 0; nj < 8; nj++)
            #pragma unroll
            for (int q = 0; q < 4; q++) acc[mi][nj][q] = 0.f;

    auto load_chunk = [&](int i) {
        const uint32_t st = sbase + (uint32_t)(i & 1) * STAGE_BYTES;
        const char* gah = (const char*)(Ahi + ((size_t)mt * NC + i) * TILE_ELEMS);
        const char* gal = (const char*)(Alo + ((size_t)mt * NC + i) * TILE_ELEMS);
        const char* gbh = (const char*)(Bhi + ((size_t)nt * NC + i) * TILE_ELEMS);
        const char* gbl = (const char*)(Blo + ((size_t)nt * NC + i) * TILE_ELEMS);
        #pragma unroll 4
        for (int j = tid; j < 1024; j += 256) {
            cp16(st + j * 16,         gah + j * 16);
            cp16(st + 16384 + j * 16, gal + j * 16);
            cp16(st + 32768 + j * 16, gbh + j * 16);
            cp16(st + 49152 + j * 16, gbl + j * 16);
        }
        asm volatile("cp.async.commit_group;" ::: "memory");
    };

    load_chunk(0);
    for (int i = 0; i < NC; i++) {
        if (i + 1 < NC) {
            load_chunk(i + 1);
            asm volatile("cp.async.wait_group 1;" ::: "memory");
        } else {
            asm volatile("cp.async.wait_group 0;" ::: "memory");
        }
        __syncthreads();

        const uint32_t st = sbase + (uint32_t)(i & 1) * STAGE_BYTES;
        const uint32_t sAh = st, sAl = st + 16384, sBh = st + 32768, sBl = st + 49152;

        #pragma unroll
        for (int ks = 0; ks < 4; ks++) {
            const uint32_t ka = (uint32_t)(ks * 32) + kA;
            const uint32_t kb = (uint32_t)(ks * 32) + kB;
            uint32_t ah[2][4], al[2][4], bh[4][4], bl[4][4];
            #pragma unroll
            for (int mi = 0; mi < 2; mi++) {
                ldsm4(ah[mi], sAh + aRow[mi] + (ka ^ xr));
                ldsm4(al[mi], sAl + aRow[mi] + (ka ^ xr));
            }
            #pragma unroll
            for (int np = 0; np < 4; np++) {
                ldsm4(bh[np], sBh + bRow[np] + (kb ^ xr));
                ldsm4(bl[np], sBl + bRow[np] + (kb ^ xr));
            }
            #pragma unroll
            for (int mi = 0; mi < 2; mi++)
                #pragma unroll
                for (int nj = 0; nj < 8; nj++) {
                    const uint32_t* bhp = &bh[nj >> 1][(nj & 1) * 2];
                    const uint32_t* blp = &bl[nj >> 1][(nj & 1) * 2];
                    mma_bf16(acc[mi][nj], ah[mi], bhp);
                    mma_bf16(acc[mi][nj], ah[mi], blp);
                    mma_bf16(acc[mi][nj], al[mi], bhp);
                }
        }
        __syncthreads();
    }

    // ---- epilogue (register -> global) ----
    const int m_base = mt * 128 + wm * 32 + (lane >> 2);
    const int n_base = nt * 128 + wn * 64 + (lane & 3) * 2;
    #pragma unroll
    for (int mi = 0; mi < 2; mi++) {
        #pragma unroll
        for (int nj = 0; nj < 8; nj++) {
            const int n = n_base + nj * 8;
            const float b0 = bias[n], b1 = bias[n + 1];
            float v00 = acc[mi][nj][0] + b0, v01 = acc[mi][nj][1] + b1;
            float v10 = acc[mi][nj][2] + b0, v11 = acc[mi][nj][3] + b1;
            if (ACT == 1) {
                v00 = v00 / (1.0f + fexp(-v00));
                v01 = v01 / (1.0f + fexp(-v01));
                v10 = v10 / (1.0f + fexp(-v10));
                v11 = v11 / (1.0f + fexp(-v11));
            }
            const int m0 = m_base + mi * 16, m1 = m0 + 8;
            if (OUTT == 1) {
                const int kc = n >> 6, kk = n & 63;
                const size_t tb = ((size_t)mt * (N >> 6) + kc) * TILE_ELEMS;
                const uint32_t o0 = sw128((m0 & 127) * 128 + kk * 2) >> 1;
                const uint32_t o1 = sw128((m1 & 127) * 128 + kk * 2) >> 1;
                split_store(Ohi, Olo, tb + o0,     v00);
                split_store(Ohi, Olo, tb + o0 + 1, v01);
                split_store(Ohi, Olo, tb + o1,     v10);
                split_store(Ohi, Olo, tb + o1 + 1, v11);
            } else {
                const size_t o0 = (size_t)m0 * N + n;
                const size_t o1 = (size_t)m1 * N + n;
                if (RES == 1) {
                    float2 r0 = *(const float2*)(resid + o0);
                    float2 r1 = *(const float2*)(resid + o1);
                    v00 += r0.x; v01 += r0.y; v10 += r1.x; v11 += r1.y;
                }
                *(float2*)(C + o0) = make_float2(v00, v01);
                *(float2*)(C + o1) = make_float2(v10, v11);
            }
        }
    }
}

// ---------------- causal flash attention (fp32) -> tiled bf16 ctx -----------
#define SKT 32
__global__ void __launch_bounds__(128) flash_attn_kernel(
    const float* __restrict__ qk, const float* __restrict__ v,
    __nv_bfloat16* __restrict__ ctx_hi, __nv_bfloat16* __restrict__ ctx_lo)
{
    const int t = blockIdx.x * 128 + threadIdx.x;
    const int h = blockIdx.y;
    const int b = blockIdx.z;
    const int row = b * SEQ + t;

    float4 q[16];
    const float4* qp = (const float4*)(qk + (size_t)row * (2 * DM) + h * HD);
    #pragma unroll
    for (int i = 0; i < 16; i++) q[i] = qp[i];

    float4 o[16];
    #pragma unroll
    for (int i = 0; i < 16; i++) o[i] = make_float4(0.f, 0.f, 0.f, 0.f);
    float m = -1e30f, l = 0.f;

    __shared__ float4 Ks[SKT][16];
    __shared__ float4 Vs[SKT][16];

    const int kend = blockIdx.x * 128 + 127;
    for (int k0 = 0; k0 <= kend; k0 += SKT) {
        __syncthreads();
        #pragma unroll
        for (int i = threadIdx.x; i < SKT * 16; i += 128) {
            const int r = i >> 4, c = i & 15;
            const int krow = b * SEQ + k0 + r;
            Ks[r][c] = *(const float4*)(qk + (size_t)krow * (2 * DM) + DM + h * HD + c * 4);
            Vs[r][c] = *(const float4*)(v + (size_t)krow * DM + h * HD + c * 4);
        }
        __syncthreads();
        if (k0 > t) continue;

        float s[SKT];
        float tmax = -1e30f;
        #pragma unroll
        for (int kk = 0; kk < SKT; kk++) {
            float acc = 0.f;
            #pragma unroll
            for (int c = 0; c < 16; c++) {
                float4 kv = Ks[kk][c];
                acc = fmaf(q[c].x, kv.x, acc);
                acc = fmaf(q[c].y, kv.y, acc);
                acc = fmaf(q[c].z, kv.z, acc);
                acc = fmaf(q[c].w, kv.w, acc);
            }
            s[kk] = (k0 + kk <= t) ? acc * 0.125f : -1e30f;
            tmax = fmaxf(tmax, s[kk]);
        }
        const float mnew = fmaxf(m, tmax);
        const float corr = fexp(m - mnew);
        l *= corr;
        #pragma unroll
        for (int c = 0; c < 16; c++) {
            o[c].x *= corr; o[c].y *= corr; o[c].z *= corr; o[c].w *= corr;
        }
        #pragma unroll
        for (int kk = 0; kk < SKT; kk++) {
            const float p = fexp(s[kk] - mnew);
            l += p;
            #pragma unroll
            for (int c = 0; c < 16; c++) {
                float4 vv = Vs[kk][c];
                o[c].x = fmaf(p, vv.x, o[c].x);
                o[c].y = fmaf(p, vv.y, o[c].y);
                o[c].z = fmaf(p, vv.z, o[c].z);
                o[c].w = fmaf(p, vv.w, o[c].w);
            }
        }
        m = mnew;
    }

    const float inv = 1.0f / l;
    const int mt = row >> 7, rr = row & 127;
    const size_t base = ((size_t)mt * (DM / 64) + h) * TILE_ELEMS;
    #pragma unroll
    for (int c = 0; c < 16; c++) {
        float4 ov = o[c];
        ov.x *= inv; ov.y *= inv; ov.z *= inv; ov.w *= inv;
        const uint32_t off = sw128(rr * 128 + c * 8) >> 1;
        split_store(ctx_hi, ctx_lo, base + off + 0, ov.x);
        split_store(ctx_hi, ctx_lo, base + off + 1, ov.y);
        split_store(ctx_hi, ctx_lo, base + off + 2, ov.z);
        split_store(ctx_hi, ctx_lo, base + off + 3, ov.w);
    }
}

// ---------------- launch ---------------------------------------------------
#define SYMADDR(p, s) cudaGetSymbolAddress((void**)&(p), s)

extern "C" void kernel_launch(void* const* d_in, const int* in_sizes, int n_in,
                              void* d_out, int out_size)
{
    const float* x         = (const float*)d_in[0];
    const float* rms_scale = (const float*)d_in[1];
    const float* in_proj_w = (const float*)d_in[2];
    const float* in_proj_b = (const float*)d_in[3];
    const float* out_proj_w= (const float*)d_in[4];
    const float* out_proj_b= (const float*)d_in[5];
    const float* w1        = (const float*)d_in[6];
    const float* b1        = (const float*)d_in[7];
    const float* w2        = (const float*)d_in[8];
    const float* b2        = (const float*)d_in[9];
    float* out = (float*)d_out;

    float *p_qk, *p_v, *p_y;
    __nv_bfloat16 *xr_h, *xr_l, *xn_h, *xn_l, *ctx_h, *ctx_l, *yn_h, *yn_l, *h_h, *h_l;
    __nv_bfloat16 *wqk_h, *wqk_l, *wv_h, *wv_l, *wo_h, *wo_l, *w1_h, *w1_l, *w2_h, *w2_l;
    SYMADDR(p_qk, g_qk);  SYMADDR(p_v, g_v);  SYMADDR(p_y, g_y);
    SYMADDR(xr_h, t_xr_hi);  SYMADDR(xr_l, t_xr_lo);
    SYMADDR(xn_h, t_xn_hi);  SYMADDR(xn_l, t_xn_lo);
    SYMADDR(ctx_h, t_ctx_hi); SYMADDR(ctx_l, t_ctx_lo);
    SYMADDR(yn_h, t_yn_hi);  SYMADDR(yn_l, t_yn_lo);
    SYMADDR(h_h, t_h_hi);    SYMADDR(h_l, t_h_lo);
    SYMADDR(wqk_h, t_wqk_hi); SYMADDR(wqk_l, t_wqk_lo);
    SYMADDR(wv_h, t_wv_hi);   SYMADDR(wv_l, t_wv_lo);
    SYMADDR(wo_h, t_wo_hi);   SYMADDR(wo_l, t_wo_lo);
    SYMADDR(w1_h, t_w1_hi);   SYMADDR(w1_l, t_w1_lo);
    SYMADDR(w2_h, t_w2_hi);   SYMADDR(w2_l, t_w2_lo);

    cudaFuncSetAttribute(gemm_mma<0,0,0>, cudaFuncAttributeMaxDynamicSharedMemorySize, GEMM_SMEM);
    cudaFuncSetAttribute(gemm_mma<1,0,1>, cudaFuncAttributeMaxDynamicSharedMemorySize, GEMM_SMEM);
    cudaFuncSetAttribute(gemm_mma<0,1,0>, cudaFuncAttributeMaxDynamicSharedMemorySize, GEMM_SMEM);

    // weight conversions -> tiled bf16 hi/lo (128-row tiles)
    conv_tiled_kernel<<<dim3(16, 16), 256>>>(in_proj_w,                     DM, wqk_h, wqk_l);
    conv_tiled_kernel<<<dim3(16, 8),  256>>>(in_proj_w + (size_t)2048 * DM, DM, wv_h,  wv_l);
    conv_tiled_kernel<<<dim3(16, 8),  256>>>(out_proj_w,                    DM, wo_h,  wo_l);
    conv_tiled_kernel<<<dim3(16, 32), 256>>>(w1,                            DM, w1_h,  w1_l);
    conv_tiled_kernel<<<dim3(64, 8),  256>>>(w2,                            FF, w2_h,  w2_l);

    // 1) xn = rmsnorm(x); xr = rope(xn)
    rms_rope_kernel<<<MROWS, 256>>>(x, rms_scale, xn_h, xn_l, xr_h, xr_l);

    // 2) [q|k] = xr @ [Wq;Wk]^T + b   (N = 2048)
    gemm_mma<0,0,0><<<dim3(16, 32), 256, GEMM_SMEM>>>(
        xr_h, xr_l, wqk_h, wqk_l, in_proj_b, nullptr, p_qk, nullptr, nullptr, 2 * DM, DM);

    // 3) v = xn @ Wv^T + bv
    gemm_mma<0,0,0><<<dim3(8, 32), 256, GEMM_SMEM>>>(
        xn_h, xn_l, wv_h, wv_l, in_proj_b + 2 * DM, nullptr, p_v, nullptr, nullptr, DM, DM);

    // 4) causal attention -> ctx (tiled bf16)
    flash_attn_kernel<<<dim3(SEQ / 128, NH, BATCH), 128>>>(p_qk, p_v, ctx_h, ctx_l);

    // 5) y = ctx @ Wo^T + b
    gemm_mma<0,0,0><<<dim3(8, 32), 256, GEMM_SMEM>>>(
        ctx_h, ctx_l, wo_h, wo_l, out_proj_b, nullptr, p_y, nullptr, nullptr, DM, DM);

    // 6) yn = rmsnorm(y)
    rms_rope_kernel<<<MROWS, 256>>>(p_y, rms_scale, yn_h, yn_l, nullptr, nullptr);

    // 7) h = silu(yn @ w1^T + b1) -> tiled bf16 directly
    gemm_mma<1,0,1><<<dim3(32, 32), 256, GEMM_SMEM>>>(
        yn_h, yn_l, w1_h, w1_l, b1, nullptr, nullptr, h_h, h_l, FF, DM);

    // 8) out = y + (h @ w2^T + b2)
    gemm_mma<0,1,0><<<dim3(8, 32), 256, GEMM_SMEM>>>(
        h_h, h_l, w2_h, w2_l, b2, p_y, out, nullptr, nullptr, DM, FF);
}

// round 4
// speedup vs baseline: 2.8951x; 1.7170x over previous
#include <cuda_runtime.h>
#include <cuda_bf16.h>
#include <cstdint>
#include <math.h>

// Problem constants
#define BATCH 2
#define SEQ   2048
#define DM    1024
#define NH    16
#define HD    64
#define FF    4096
#define MROWS (BATCH * SEQ)   // 4096

#define TILE_ELEMS 8192                 // 128 rows x 64 bf16 (SW128)
#define STAGE_BYTES 65536
#define GEMM_SMEM   (2 * STAGE_BYTES + 256)
#define ATTN_SMEM   (32768 + 2 * 32768)   // Q(hi+lo) + 2 KV stages

// ---------------- scratch -----------------------------------------------
__device__ float g_y  [MROWS * DM];

__device__ __nv_bfloat16 t_xr_hi [MROWS * DM],  t_xr_lo [MROWS * DM];
__device__ __nv_bfloat16 t_xn_hi [MROWS * DM],  t_xn_lo [MROWS * DM];
__device__ __nv_bfloat16 t_q_hi  [MROWS * DM],  t_q_lo  [MROWS * DM];
__device__ __nv_bfloat16 t_k_hi  [MROWS * DM],  t_k_lo  [MROWS * DM];
__device__ __nv_bfloat16 t_v_hi  [MROWS * DM],  t_v_lo  [MROWS * DM];
__device__ __nv_bfloat16 t_ctx_hi[MROWS * DM],  t_ctx_lo[MROWS * DM];
__device__ __nv_bfloat16 t_yn_hi [MROWS * DM],  t_yn_lo [MROWS * DM];
__device__ __nv_bfloat16 t_h_hi  [MROWS * FF],  t_h_lo  [MROWS * FF];
__device__ __nv_bfloat16 t_wqk_hi[2048 * DM],   t_wqk_lo[2048 * DM];
__device__ __nv_bfloat16 t_wv_hi [DM * DM],     t_wv_lo [DM * DM];
__device__ __nv_bfloat16 t_wo_hi [DM * DM],     t_wo_lo [DM * DM];
__device__ __nv_bfloat16 t_w1_hi [FF * DM],     t_w1_lo [FF * DM];
__device__ __nv_bfloat16 t_w2_hi [DM * FF],     t_w2_lo [DM * FF];

// ---------------- helpers -----------------------------------------------
__device__ __forceinline__ uint32_t sw128(uint32_t o) { return o ^ ((o >> 3) & 0x70); }

__device__ __forceinline__ void split_store(__nv_bfloat16* hi, __nv_bfloat16* lo,
                                            size_t idx, float v)
{
    __nv_bfloat16 h = __float2bfloat16(v);
    hi[idx] = h;
    lo[idx] = __float2bfloat16(v - __bfloat162float(h));
}

__device__ __forceinline__ float fexp(float x)
{
    x = fminf(fmaxf(x, -87.f), 87.f);
    float y = x * 1.4426950408889634f;
    float r = rintf(y);
    float f = y - r;
    float p = 1.33336498e-3f;
    p = fmaf(p, f, 9.61793571e-3f);
    p = fmaf(p, f, 5.55043442e-2f);
    p = fmaf(p, f, 2.40226507e-1f);
    p = fmaf(p, f, 6.93147182e-1f);
    p = fmaf(p, f, 1.0f);
    return p * __int_as_float(((int)r + 127) << 23);
}

__device__ __forceinline__ uint32_t smem_u32(const void* p)
{
    uint32_t a;
    asm("{ .reg .u64 t; cvta.to.shared.u64 t, %1; cvt.u32.u64 %0, t; }" : "=r"(a) : "l"(p));
    return a;
}

__device__ __forceinline__ void cp16(uint32_t s, const void* g)
{
    asm volatile("cp.async.cg.shared.global [%0], [%1], 16;" :: "r"(s), "l"(g));
}

__device__ __forceinline__ void ldsm4(uint32_t* r, uint32_t addr)
{
    asm volatile("ldmatrix.sync.aligned.m8n8.x4.shared.b16 {%0,%1,%2,%3}, [%4];"
                 : "=r"(r[0]), "=r"(r[1]), "=r"(r[2]), "=r"(r[3]) : "r"(addr));
}

__device__ __forceinline__ void ldsm4t(uint32_t* r, uint32_t addr)
{
    asm volatile("ldmatrix.sync.aligned.m8n8.x4.trans.shared.b16 {%0,%1,%2,%3}, [%4];"
                 : "=r"(r[0]), "=r"(r[1]), "=r"(r[2]), "=r"(r[3]) : "r"(addr));
}

__device__ __forceinline__ void mma_bf16(float* d, const uint32_t* a, const uint32_t* b)
{
    asm volatile(
        "mma.sync.aligned.m16n8k16.row.col.f32.bf16.bf16.f32 "
        "{%0,%1,%2,%3}, {%4,%5,%6,%7}, {%8,%9}, {%0,%1,%2,%3};"
        : "+f"(d[0]), "+f"(d[1]), "+f"(d[2]), "+f"(d[3])
        : "r"(a[0]), "r"(a[1]), "r"(a[2]), "r"(a[3]), "r"(b[0]), "r"(b[1]));
}

__device__ __forceinline__ uint32_t pack_bf2(float x, float y)
{
    __nv_bfloat162 t = __floats2bfloat162_rn(x, y);
    return *(uint32_t*)&t;
}

// ---------------- RMSNorm (+ optional RoPE) -> tiled bf16 hi/lo ----------
__global__ void __launch_bounds__(256) rms_rope_kernel(
    const float* __restrict__ x, const float* __restrict__ scale,
    __nv_bfloat16* __restrict__ n_hi, __nv_bfloat16* __restrict__ n_lo,
    __nv_bfloat16* __restrict__ r_hi, __nv_bfloat16* __restrict__ r_lo)
{
    const int row = blockIdx.x;
    const int tid = threadIdx.x;
    __shared__ float red[8];
    __shared__ float th[32];

    if (tid < 32)
        th[tid] = (float)exp(-((double)(2 * tid) / 64.0) * 9.210340371976184);

    float4 v = *(const float4*)(x + (size_t)row * DM + tid * 4);
    float ss = v.x * v.x + v.y * v.y + v.z * v.z + v.w * v.w;
    #pragma unroll
    for (int o = 16; o > 0; o >>= 1) ss += __shfl_xor_sync(0xffffffffu, ss, o);
    if ((tid & 31) == 0) red[tid >> 5] = ss;
    __syncthreads();
    float tot = 0.f;
    #pragma unroll
    for (int i = 0; i < 8; i++) tot += red[i];
    const float r = rsqrtf(tot * (1.0f / (float)DM) + 1e-6f);

    float4 sc = *(const float4*)(scale + tid * 4);
    float4 n;
    n.x = v.x * r * sc.x;
    n.y = v.y * r * sc.y;
    n.z = v.z * r * sc.z;
    n.w = v.w * r * sc.w;

    const int mt = row >> 7, rr = row & 127;
    const int c0 = tid * 4;
    const int kc = c0 >> 6, kk = c0 & 63;
    const size_t base = ((size_t)mt * (DM / 64) + kc) * TILE_ELEMS;
    const uint32_t off = sw128(rr * 128 + kk * 2) >> 1;
    split_store(n_hi, n_lo, base + off + 0, n.x);
    split_store(n_hi, n_lo, base + off + 1, n.y);
    split_store(n_hi, n_lo, base + off + 2, n.z);
    split_store(n_hi, n_lo, base + off + 3, n.w);

    if (r_hi != nullptr) {
        const int t = row & (SEQ - 1);
        const int c = c0 & (HD - 1);
        const int p = c >> 1;
        float a0 = (float)t * th[p];
        float a1 = (float)t * th[p + 1];
        float s0, co0, s1, co1;
        sincosf(a0, &s0, &co0);
        sincosf(a1, &s1, &co1);
        float4 o;
        o.x = n.x * co0 - n.y * s0;
        o.y = n.y * co0 + n.x * s0;
        o.z = n.z * co1 - n.w * s1;
        o.w = n.w * co1 + n.z * s1;
        split_store(r_hi, r_lo, base + off + 0, o.x);
        split_store(r_hi, r_lo, base + off + 1, o.y);
        split_store(r_hi, r_lo, base + off + 2, o.z);
        split_store(r_hi, r_lo, base + off + 3, o.w);
    }
}

// ---------------- fp32 [N,K] -> tiled bf16 hi/lo -------------------------
__global__ void __launch_bounds__(256) conv_tiled_kernel(
    const float* __restrict__ in, int K,
    __nv_bfloat16* __restrict__ hi, __nv_bfloat16* __restrict__ lo)
{
    const int kc = blockIdx.x;
    const int rt = blockIdx.y;
    const int NCk = gridDim.x;
    const size_t base = ((size_t)rt * NCk + kc) * (size_t)TILE_ELEMS;
    for (int idx = threadIdx.x; idx < TILE_ELEMS; idx += 256) {
        const int r = idx >> 6, k = idx & 63;
        float v = in[(size_t)(rt * 128 + r) * K + kc * 64 + k];
        const uint32_t off = sw128(r * 128 + k * 2) >> 1;
        split_store(hi, lo, base + off, v);
    }
}

// ---------------- mma.sync bf16x3 GEMM -----------------------------------
template <int ACT, int RES, int OUTT>
__global__ void __launch_bounds__(256) gemm_mma(
    const __nv_bfloat16* __restrict__ Ahi, const __nv_bfloat16* __restrict__ Alo,
    const __nv_bfloat16* __restrict__ Bhi, const __nv_bfloat16* __restrict__ Blo,
    const float* __restrict__ bias, const float* __restrict__ resid,
    float* __restrict__ C, __nv_bfloat16* __restrict__ Ohi, __nv_bfloat16* __restrict__ Olo,
    int N, int K)
{
    extern __shared__ char smem[];
    const uint32_t sbase = (smem_u32(smem) + 127) & ~127u;

    const int tid = threadIdx.x;
    const int lane = tid & 31, wid = tid >> 5;
    const int wm = wid >> 1, wn = wid & 1;
    const int NC = K >> 6;
    const int mt = blockIdx.y, nt = blockIdx.x;

    const uint32_t xr = (uint32_t)((lane & 7) << 4);
    uint32_t aRow[2];
    #pragma unroll
    for (int mi = 0; mi < 2; mi++)
        aRow[mi] = (uint32_t)((wm * 32 + mi * 16 + (lane & 15)) * 128);
    const uint32_t kA = (uint32_t)((lane >> 4) * 16);

    const int nb = wn * 64 + ((lane >> 4) << 3) + (lane & 7);
    uint32_t bRow[4];
    #pragma unroll
    for (int np = 0; np < 4; np++)
        bRow[np] = (uint32_t)((nb + np * 16) * 128);
    const uint32_t kB = (uint32_t)(((lane >> 3) & 1) * 16);

    float acc[2][8][4];
    #pragma unroll
    for (int mi = 0; mi < 2; mi++)
        #pragma unroll
        for (int nj = 0; nj < 8; nj++)
            #pragma unroll
            for (int q = 0; q < 4; q++) acc[mi][nj][q] = 0.f;

    auto load_chunk = [&](int i) {
        const uint32_t st = sbase + (uint32_t)(i & 1) * STAGE_BYTES;
        const char* gah = (const char*)(Ahi + ((size_t)mt * NC + i) * TILE_ELEMS);
        const char* gal = (const char*)(Alo + ((size_t)mt * NC + i) * TILE_ELEMS);
        const char* gbh = (const char*)(Bhi + ((size_t)nt * NC + i) * TILE_ELEMS);
        const char* gbl = (const char*)(Blo + ((size_t)nt * NC + i) * TILE_ELEMS);
        #pragma unroll 4
        for (int j = tid; j < 1024; j += 256) {
            cp16(st + j * 16,         gah + j * 16);
            cp16(st + 16384 + j * 16, gal + j * 16);
            cp16(st + 32768 + j * 16, gbh + j * 16);
            cp16(st + 49152 + j * 16, gbl + j * 16);
        }
        asm volatile("cp.async.commit_group;" ::: "memory");
    };

    load_chunk(0);
    for (int i = 0; i < NC; i++) {
        if (i + 1 < NC) {
            load_chunk(i + 1);
            asm volatile("cp.async.wait_group 1;" ::: "memory");
        } else {
            asm volatile("cp.async.wait_group 0;" ::: "memory");
        }
        __syncthreads();

        const uint32_t st = sbase + (uint32_t)(i & 1) * STAGE_BYTES;
        const uint32_t sAh = st, sAl = st + 16384, sBh = st + 32768, sBl = st + 49152;

        #pragma unroll
        for (int ks = 0; ks < 4; ks++) {
            const uint32_t ka = (uint32_t)(ks * 32) + kA;
            const uint32_t kb = (uint32_t)(ks * 32) + kB;
            uint32_t ah[2][4], al[2][4], bh[4][4], bl[4][4];
            #pragma unroll
            for (int mi = 0; mi < 2; mi++) {
                ldsm4(ah[mi], sAh + aRow[mi] + (ka ^ xr));
                ldsm4(al[mi], sAl + aRow[mi] + (ka ^ xr));
            }
            #pragma unroll
            for (int np = 0; np < 4; np++) {
                ldsm4(bh[np], sBh + bRow[np] + (kb ^ xr));
                ldsm4(bl[np], sBl + bRow[np] + (kb ^ xr));
            }
            #pragma unroll
            for (int mi = 0; mi < 2; mi++)
                #pragma unroll
                for (int nj = 0; nj < 8; nj++) {
                    const uint32_t* bhp = &bh[nj >> 1][(nj & 1) * 2];
                    const uint32_t* blp = &bl[nj >> 1][(nj & 1) * 2];
                    mma_bf16(acc[mi][nj], ah[mi], bhp);
                    mma_bf16(acc[mi][nj], ah[mi], blp);
                    mma_bf16(acc[mi][nj], al[mi], bhp);
                }
        }
        __syncthreads();
    }

    const int m_base = mt * 128 + wm * 32 + (lane >> 2);
    const int n_base = nt * 128 + wn * 64 + (lane & 3) * 2;
    #pragma unroll
    for (int mi = 0; mi < 2; mi++) {
        #pragma unroll
        for (int nj = 0; nj < 8; nj++) {
            const int n = n_base + nj * 8;
            const float b0 = bias[n], b1 = bias[n + 1];
            float v00 = acc[mi][nj][0] + b0, v01 = acc[mi][nj][1] + b1;
            float v10 = acc[mi][nj][2] + b0, v11 = acc[mi][nj][3] + b1;
            if (ACT == 1) {
                v00 = v00 / (1.0f + fexp(-v00));
                v01 = v01 / (1.0f + fexp(-v01));
                v10 = v10 / (1.0f + fexp(-v10));
                v11 = v11 / (1.0f + fexp(-v11));
            }
            const int m0 = m_base + mi * 16, m1 = m0 + 8;
            if (OUTT == 1) {
                const int kc = n >> 6, kk = n & 63;
                const size_t tb = ((size_t)mt * (N >> 6) + kc) * TILE_ELEMS;
                const uint32_t o0 = sw128((m0 & 127) * 128 + kk * 2) >> 1;
                const uint32_t o1 = sw128((m1 & 127) * 128 + kk * 2) >> 1;
                split_store(Ohi, Olo, tb + o0,     v00);
                split_store(Ohi, Olo, tb + o0 + 1, v01);
                split_store(Ohi, Olo, tb + o1,     v10);
                split_store(Ohi, Olo, tb + o1 + 1, v11);
            } else {
                const size_t o0 = (size_t)m0 * N + n;
                const size_t o1 = (size_t)m1 * N + n;
                if (RES == 1) {
                    float2 r0 = *(const float2*)(resid + o0);
                    float2 r1 = *(const float2*)(resid + o1);
                    v00 += r0.x; v01 += r0.y; v10 += r1.x; v11 += r1.y;
                }
                *(float2*)(C + o0) = make_float2(v00, v01);
                *(float2*)(C + o1) = make_float2(v10, v11);
            }
        }
    }
}

// ---------------- tensor-core causal flash attention ---------------------
// grid (16 qtiles, 16 heads, 2 batch), 256 thr = 8 warps x 16 q-rows
__global__ void __launch_bounds__(256) flash_mma_kernel(
    const __nv_bfloat16* __restrict__ Qhi, const __nv_bfloat16* __restrict__ Qlo,
    const __nv_bfloat16* __restrict__ Khi, const __nv_bfloat16* __restrict__ Klo,
    const __nv_bfloat16* __restrict__ Vhi, const __nv_bfloat16* __restrict__ Vlo,
    __nv_bfloat16* __restrict__ Chi, __nv_bfloat16* __restrict__ Clo)
{
    extern __shared__ char smem[];
    const uint32_t sbase = smem_u32(smem);

    const int tid = threadIdx.x, lane = tid & 31, wq = tid >> 5;
    const int qt = 15 - blockIdx.x;           // big tiles first
    const int h = blockIdx.y, b = blockIdx.z;
    const int mtq = b * 16 + qt;
    const int KT = 2 * qt + 2;

    const uint32_t sQh = sbase, sQl = sbase + 16384;

    // Q tile (hi+lo) async load
    {
        const char* gQh = (const char*)(Qhi + ((size_t)mtq * 16 + h) * TILE_ELEMS);
        const char* gQl = (const char*)(Qlo + ((size_t)mtq * 16 + h) * TILE_ELEMS);
        for (int j = tid; j < 1024; j += 256) {
            cp16(sQh + j * 16, gQh + j * 16);
            cp16(sQl + j * 16, gQl + j * 16);
        }
        asm volatile("cp.async.commit_group;" ::: "memory");
    }

    auto load_kv = [&](int kt) {
        const uint32_t st = sbase + 32768 + (uint32_t)(kt & 1) * 32768;
        const int mtk = b * 16 + (kt >> 1);
        const size_t toff = ((size_t)mtk * 16 + h) * TILE_ELEMS + (size_t)(kt & 1) * 4096;
        const char* gkh = (const char*)(Khi + toff);
        const char* gkl = (const char*)(Klo + toff);
        const char* gvh = (const char*)(Vhi + toff);
        const char* gvl = (const char*)(Vlo + toff);
        for (int j = tid; j < 512; j += 256) {
            cp16(st + j * 16,         gkh + j * 16);
            cp16(st + 8192 + j * 16,  gkl + j * 16);
            cp16(st + 16384 + j * 16, gvh + j * 16);
            cp16(st + 24576 + j * 16, gvl + j * 16);
        }
        asm volatile("cp.async.commit_group;" ::: "memory");
    };
    load_kv(0);
    asm volatile("cp.async.wait_group 0;" ::: "memory");
    __syncthreads();

    // Q A-fragments (held for whole kernel)
    const uint32_t xr = (uint32_t)((lane & 7) << 4);
    const uint32_t aRow = (uint32_t)((wq * 16 + (lane & 15)) * 128);
    const uint32_t kA = (uint32_t)((lane >> 4) * 16);
    uint32_t qh[4][4], ql[4][4];
    #pragma unroll
    for (int ks = 0; ks < 4; ks++) {
        const uint32_t ka = (uint32_t)(ks * 32) + kA;
        ldsm4(qh[ks], sQh + aRow + (ka ^ xr));
        ldsm4(ql[ks], sQl + aRow + (ka ^ xr));
    }

    float o[8][4];
    #pragma unroll
    for (int nj = 0; nj < 8; nj++)
        #pragma unroll
        for (int q = 0; q < 4; q++) o[nj][q] = 0.f;
    float m0 = -1e30f, m1 = -1e30f, l0 = 0.f, l1 = 0.f;

    // K-phase B addressing (same pattern as gemm)
    const uint32_t nbK = (uint32_t)(((lane >> 4) << 3) + (lane & 7));
    const uint32_t kB = (uint32_t)(((lane >> 3) & 1) * 16);
    // V-phase trans addressing
    const int vmi = lane >> 3, vri = lane & 7;

    const int row_lo = qt * 128 + wq * 16;     // lowest q row of this warp

    for (int kt = 0; kt < KT; kt++) {
        if (kt + 1 < KT) {
            load_kv(kt + 1);
            asm volatile("cp.async.wait_group 1;" ::: "memory");
        } else {
            asm volatile("cp.async.wait_group 0;" ::: "memory");
        }
        __syncthreads();

        if (kt * 64 <= row_lo + 15) {          // warp has unmasked work
            const uint32_t st = sbase + 32768 + (uint32_t)(kt & 1) * 32768;
            const uint32_t sKh = st, sKl = st + 8192;
            const uint32_t sVh = st + 16384, sVl = st + 24576;

            float S[8][4];
            #pragma unroll
            for (int nj = 0; nj < 8; nj++)
                #pragma unroll
                for (int q = 0; q < 4; q++) S[nj][q] = 0.f;

            #pragma unroll
            for (int ks = 0; ks < 4; ks++) {
                const uint32_t kb = (uint32_t)(ks * 32) + kB;
                uint32_t bh[4][4], bl[4][4];
                #pragma unroll
                for (int np = 0; np < 4; np++) {
                    const uint32_t r = (nbK + np * 16) * 128;
                    ldsm4(bh[np], sKh + r + (kb ^ xr));
                    ldsm4(bl[np], sKl + r + (kb ^ xr));
                }
                #pragma unroll
                for (int nj = 0; nj < 8; nj++) {
                    const uint32_t* bhp = &bh[nj >> 1][(nj & 1) * 2];
                    const uint32_t* blp = &bl[nj >> 1][(nj & 1) * 2];
                    mma_bf16(S[nj], qh[ks], bhp);
                    mma_bf16(S[nj], qh[ks], blp);
                    mma_bf16(S[nj], ql[ks], bhp);
                }
            }

            // scale + causal mask
            const int r0 = row_lo + (lane >> 2);
            const bool need_mask = (kt * 64 + 63) > row_lo;
            #pragma unroll
            for (int nj = 0; nj < 8; nj++)
                #pragma unroll
                for (int q = 0; q < 4; q++) S[nj][q] *= 0.125f;
            if (need_mask) {
                #pragma unroll
                for (int nj = 0; nj < 8; nj++)
                    #pragma unroll
                    for (int q = 0; q < 4; q++) {
                        const int kg = kt * 64 + nj * 8 + (lane & 3) * 2 + (q & 1);
                        const int qg = r0 + ((q >= 2) ? 8 : 0);
                        if (kg > qg) S[nj][q] = -1e30f;
                    }
            }

            // online softmax (rows r0 and r0+8; 4 lanes per row)
            float t0 = -1e30f, t1 = -1e30f;
            #pragma unroll
            for (int nj = 0; nj < 8; nj++) {
                t0 = fmaxf(t0, fmaxf(S[nj][0], S[nj][1]));
                t1 = fmaxf(t1, fmaxf(S[nj][2], S[nj][3]));
            }
            t0 = fmaxf(t0, __shfl_xor_sync(0xffffffffu, t0, 1));
            t0 = fmaxf(t0, __shfl_xor_sync(0xffffffffu, t0, 2));
            t1 = fmaxf(t1, __shfl_xor_sync(0xffffffffu, t1, 1));
            t1 = fmaxf(t1, __shfl_xor_sync(0xffffffffu, t1, 2));
            const float mn0 = fmaxf(m0, t0), mn1 = fmaxf(m1, t1);
            const float c0 = fexp(m0 - mn0), c1 = fexp(m1 - mn1);
            m0 = mn0; m1 = mn1;
            l0 *= c0; l1 *= c1;
            #pragma unroll
            for (int nj = 0; nj < 8; nj++) {
                o[nj][0] *= c0; o[nj][1] *= c0;
                o[nj][2] *= c1; o[nj][3] *= c1;
            }
            float ls0 = 0.f, ls1 = 0.f;
            #pragma unroll
            for (int nj = 0; nj < 8; nj++) {
                S[nj][0] = fexp(S[nj][0] - mn0); ls0 += S[nj][0];
                S[nj][1] = fexp(S[nj][1] - mn0); ls0 += S[nj][1];
                S[nj][2] = fexp(S[nj][2] - mn1); ls1 += S[nj][2];
                S[nj][3] = fexp(S[nj][3] - mn1); ls1 += S[nj][3];
            }
            l0 += ls0; l1 += ls1;

            // P @ V (3-term split; V via ldmatrix.trans)
            #pragma unroll
            for (int kk = 0; kk < 4; kk++) {
                uint32_t ah[4], al[4];
                {
                    float p00 = S[2*kk][0],   p01 = S[2*kk][1];
                    float p10 = S[2*kk][2],   p11 = S[2*kk][3];
                    float p20 = S[2*kk+1][0], p21 = S[2*kk+1][1];
                    float p30 = S[2*kk+1][2], p31 = S[2*kk+1][3];
                    ah[0] = pack_bf2(p00, p01);
                    ah[1] = pack_bf2(p10, p11);
                    ah[2] = pack_bf2(p20, p21);
                    ah[3] = pack_bf2(p30, p31);
                    __nv_bfloat162 h0 = *(__nv_bfloat162*)&ah[0];
                    __nv_bfloat162 h1 = *(__nv_bfloat162*)&ah[1];
                    __nv_bfloat162 h2 = *(__nv_bfloat162*)&ah[2];
                    __nv_bfloat162 h3 = *(__nv_bfloat162*)&ah[3];
                    al[0] = pack_bf2(p00 - __bfloat162float(h0.x), p01 - __bfloat162float(h0.y));
                    al[1] = pack_bf2(p10 - __bfloat162float(h1.x), p11 - __bfloat162float(h1.y));
                    al[2] = pack_bf2(p20 - __bfloat162float(h2.x), p21 - __bfloat162float(h2.y));
                    al[3] = pack_bf2(p30 - __bfloat162float(h3.x), p31 - __bfloat162float(h3.y));
                }
                uint32_t vh[4][4], vl[4][4];
                const uint32_t vrow = (uint32_t)(kk * 16 + (vmi & 1) * 8 + vri);
                #pragma unroll
                for (int g = 0; g < 4; g++) {
                    const uint32_t off = sw128(vrow * 128 + (uint32_t)(g * 16 + (vmi >> 1) * 8) * 2);
                    ldsm4t(vh[g], sVh + off);
                    ldsm4t(vl[g], sVl + off);
                }
                #pragma unroll
                for (int nj = 0; nj < 8; nj++) {
                    const uint32_t* bvh = &vh[nj >> 1][(nj & 1) * 2];
                    const uint32_t* bvl = &vl[nj >> 1][(nj & 1) * 2];
                    mma_bf16(o[nj], ah, bvh);
                    mma_bf16(o[nj], ah, bvl);
                    mma_bf16(o[nj], al, bvh);
                }
            }
        }
        __syncthreads();
    }

    // final normalize + tiled bf16 output
    l0 += __shfl_xor_sync(0xffffffffu, l0, 1);
    l0 += __shfl_xor_sync(0xffffffffu, l0, 2);
    l1 += __shfl_xor_sync(0xffffffffu, l1, 1);
    l1 += __shfl_xor_sync(0xffffffffu, l1, 2);
    const float inv0 = 1.0f / l0, inv1 = 1.0f / l1;

    const size_t tb = ((size_t)mtq * 16 + h) * TILE_ELEMS;
    const int rl0 = wq * 16 + (lane >> 2), rl1 = rl0 + 8;
    #pragma unroll
    for (int nj = 0; nj < 8; nj++) {
        const int col = nj * 8 + (lane & 3) * 2;
        const uint32_t o0 = sw128(rl0 * 128 + col * 2) >> 1;
        const uint32_t o1 = sw128(rl1 * 128 + col * 2) >> 1;
        split_store(Chi, Clo, tb + o0,     o[nj][0] * inv0);
        split_store(Chi, Clo, tb + o0 + 1, o[nj][1] * inv0);
        split_store(Chi, Clo, tb + o1,     o[nj][2] * inv1);
        split_store(Chi, Clo, tb + o1 + 1, o[nj][3] * inv1);
    }
}

// ---------------- launch -------------------------------------------------
#define SYMADDR(p, s) cudaGetSymbolAddress((void**)&(p), s)

extern "C" void kernel_launch(void* const* d_in, const int* in_sizes, int n_in,
                              void* d_out, int out_size)
{
    const float* x         = (const float*)d_in[0];
    const float* rms_scale = (const float*)d_in[1];
    const float* in_proj_w = (const float*)d_in[2];
    const float* in_proj_b = (const float*)d_in[3];
    const float* out_proj_w= (const float*)d_in[4];
    const float* out_proj_b= (const float*)d_in[5];
    const float* w1        = (const float*)d_in[6];
    const float* b1        = (const float*)d_in[7];
    const float* w2        = (const float*)d_in[8];
    const float* b2        = (const float*)d_in[9];
    float* out = (float*)d_out;

    float *p_y;
    __nv_bfloat16 *xr_h, *xr_l, *xn_h, *xn_l, *q_h, *q_l, *k_h, *k_l, *v_h, *v_l;
    __nv_bfloat16 *ctx_h, *ctx_l, *yn_h, *yn_l, *h_h, *h_l;
    __nv_bfloat16 *wqk_h, *wqk_l, *wv_h, *wv_l, *wo_h, *wo_l, *w1_h, *w1_l, *w2_h, *w2_l;
    SYMADDR(p_y, g_y);
    SYMADDR(xr_h, t_xr_hi);  SYMADDR(xr_l, t_xr_lo);
    SYMADDR(xn_h, t_xn_hi);  SYMADDR(xn_l, t_xn_lo);
    SYMADDR(q_h, t_q_hi);    SYMADDR(q_l, t_q_lo);
    SYMADDR(k_h, t_k_hi);    SYMADDR(k_l, t_k_lo);
    SYMADDR(v_h, t_v_hi);    SYMADDR(v_l, t_v_lo);
    SYMADDR(ctx_h, t_ctx_hi); SYMADDR(ctx_l, t_ctx_lo);
    SYMADDR(yn_h, t_yn_hi);  SYMADDR(yn_l, t_yn_lo);
    SYMADDR(h_h, t_h_hi);    SYMADDR(h_l, t_h_lo);
    SYMADDR(wqk_h, t_wqk_hi); SYMADDR(wqk_l, t_wqk_lo);
    SYMADDR(wv_h, t_wv_hi);   SYMADDR(wv_l, t_wv_lo);
    SYMADDR(wo_h, t_wo_hi);   SYMADDR(wo_l, t_wo_lo);
    SYMADDR(w1_h, t_w1_hi);   SYMADDR(w1_l, t_w1_lo);
    SYMADDR(w2_h, t_w2_hi);   SYMADDR(w2_l, t_w2_lo);

    cudaFuncSetAttribute(gemm_mma<0,0,0>, cudaFuncAttributeMaxDynamicSharedMemorySize, GEMM_SMEM);
    cudaFuncSetAttribute(gemm_mma<0,0,1>, cudaFuncAttributeMaxDynamicSharedMemorySize, GEMM_SMEM);
    cudaFuncSetAttribute(gemm_mma<1,0,1>, cudaFuncAttributeMaxDynamicSharedMemorySize, GEMM_SMEM);
    cudaFuncSetAttribute(gemm_mma<0,1,0>, cudaFuncAttributeMaxDynamicSharedMemorySize, GEMM_SMEM);
    cudaFuncSetAttribute(flash_mma_kernel, cudaFuncAttributeMaxDynamicSharedMemorySize, ATTN_SMEM);

    // weight conversions -> tiled bf16 hi/lo
    conv_tiled_kernel<<<dim3(16, 16), 256>>>(in_proj_w,                     DM, wqk_h, wqk_l);
    conv_tiled_kernel<<<dim3(16, 8),  256>>>(in_proj_w + (size_t)2048 * DM, DM, wv_h,  wv_l);
    conv_tiled_kernel<<<dim3(16, 8),  256>>>(out_proj_w,                    DM, wo_h,  wo_l);
    conv_tiled_kernel<<<dim3(16, 32), 256>>>(w1,                            DM, w1_h,  w1_l);
    conv_tiled_kernel<<<dim3(64, 8),  256>>>(w2,                            FF, w2_h,  w2_l);

    // 1) xn = rmsnorm(x); xr = rope(xn)
    rms_rope_kernel<<<MROWS, 256>>>(x, rms_scale, xn_h, xn_l, xr_h, xr_l);

    // 2) q/k/v projections -> attention tiles (mt, head)
    gemm_mma<0,0,1><<<dim3(8, 32), 256, GEMM_SMEM>>>(
        xr_h, xr_l, wqk_h, wqk_l, in_proj_b, nullptr,
        nullptr, q_h, q_l, DM, DM);
    gemm_mma<0,0,1><<<dim3(8, 32), 256, GEMM_SMEM>>>(
        xr_h, xr_l, wqk_h + (size_t)1024 * DM, wqk_l + (size_t)1024 * DM,
        in_proj_b + DM, nullptr, nullptr, k_h, k_l, DM, DM);
    gemm_mma<0,0,1><<<dim3(8, 32), 256, GEMM_SMEM>>>(
        xn_h, xn_l, wv_h, wv_l, in_proj_b + 2 * DM, nullptr,
        nullptr, v_h, v_l, DM, DM);

    // 3) tensor-core causal attention -> ctx tiles
    flash_mma_kernel<<<dim3(16, NH, BATCH), 256, ATTN_SMEM>>>(
        q_h, q_l, k_h, k_l, v_h, v_l, ctx_h, ctx_l);

    // 4) y = ctx @ Wo^T + b
    gemm_mma<0,0,0><<<dim3(8, 32), 256, GEMM_SMEM>>>(
        ctx_h, ctx_l, wo_h, wo_l, out_proj_b, nullptr, p_y, nullptr, nullptr, DM, DM);

    // 5) yn = rmsnorm(y)
    rms_rope_kernel<<<MROWS, 256>>>(p_y, rms_scale, yn_h, yn_l, nullptr, nullptr);

    // 6) h = silu(yn @ w1^T + b1) -> tiled bf16
    gemm_mma<1,0,1><<<dim3(32, 32), 256, GEMM_SMEM>>>(
        yn_h, yn_l, w1_h, w1_l, b1, nullptr, nullptr, h_h, h_l, FF, DM);

    // 7) out = y + (h @ w2^T + b2)
    gemm_mma<0,1,0><<<dim3(8, 32), 256, GEMM_SMEM>>>(
        h_h, h_l, w2_h, w2_l, b2, p_y, out, nullptr, nullptr, DM, FF);
}

// round 5
// speedup vs baseline: 6.4914x; 2.2422x over previous
#include <cuda_runtime.h>
#include <cuda_fp16.h>
#include <cstdint>
#include <math.h>

// Problem constants
#define BATCH 2
#define SEQ   2048
#define DM    1024
#define NH    16
#define HD    64
#define FF    4096
#define MROWS (BATCH * SEQ)   // 4096

#define TILE_ELEMS 8192                 // 128 rows x 64 fp16 (SW128)
#define TILE_BYTES 16384
#define STAGE_BYTES 32768               // A tile + B tile
#define GEMM_SMEM   (2 * STAGE_BYTES + 256)
#define ATTN_SMEM   (16384 + 2 * 16384) // Q + 2 KV stages

// ---------------- scratch -----------------------------------------------
__device__ float g_y  [MROWS * DM];

__device__ __half t_xr [MROWS * DM];
__device__ __half t_xn [MROWS * DM];
__device__ __half t_q  [MROWS * DM];
__device__ __half t_k  [MROWS * DM];
__device__ __half t_v  [MROWS * DM];
__device__ __half t_ctx[MROWS * DM];
__device__ __half t_yn [MROWS * DM];
__device__ __half t_h  [MROWS * FF];
__device__ __half t_wqk[2048 * DM];
__device__ __half t_wv [DM * DM];
__device__ __half t_wo [DM * DM];
__device__ __half t_w1 [FF * DM];
__device__ __half t_w2 [DM * FF];

// ---------------- helpers -----------------------------------------------
__device__ __forceinline__ uint32_t sw128(uint32_t o) { return o ^ ((o >> 3) & 0x70); }

__device__ __forceinline__ float fexp(float x)
{
    x = fminf(fmaxf(x, -87.f), 87.f);
    float y = x * 1.4426950408889634f;
    float r = rintf(y);
    float f = y - r;
    float p = 1.33336498e-3f;
    p = fmaf(p, f, 9.61793571e-3f);
    p = fmaf(p, f, 5.55043442e-2f);
    p = fmaf(p, f, 2.40226507e-1f);
    p = fmaf(p, f, 6.93147182e-1f);
    p = fmaf(p, f, 1.0f);
    return p * __int_as_float(((int)r + 127) << 23);
}

__device__ __forceinline__ uint32_t smem_u32(const void* p)
{
    uint32_t a;
    asm("{ .reg .u64 t; cvta.to.shared.u64 t, %1; cvt.u32.u64 %0, t; }" : "=r"(a) : "l"(p));
    return a;
}

__device__ __forceinline__ void cp16(uint32_t s, const void* g)
{
    asm volatile("cp.async.cg.shared.global [%0], [%1], 16;" :: "r"(s), "l"(g));
}

__device__ __forceinline__ void ldsm4(uint32_t* r, uint32_t addr)
{
    asm volatile("ldmatrix.sync.aligned.m8n8.x4.shared.b16 {%0,%1,%2,%3}, [%4];"
                 : "=r"(r[0]), "=r"(r[1]), "=r"(r[2]), "=r"(r[3]) : "r"(addr));
}

__device__ __forceinline__ void ldsm4t(uint32_t* r, uint32_t addr)
{
    asm volatile("ldmatrix.sync.aligned.m8n8.x4.trans.shared.b16 {%0,%1,%2,%3}, [%4];"
                 : "=r"(r[0]), "=r"(r[1]), "=r"(r[2]), "=r"(r[3]) : "r"(addr));
}

__device__ __forceinline__ void mma_f16(float* d, const uint32_t* a, const uint32_t* b)
{
    asm volatile(
        "mma.sync.aligned.m16n8k16.row.col.f32.f16.f16.f32 "
        "{%0,%1,%2,%3}, {%4,%5,%6,%7}, {%8,%9}, {%0,%1,%2,%3};"
        : "+f"(d[0]), "+f"(d[1]), "+f"(d[2]), "+f"(d[3])
        : "r"(a[0]), "r"(a[1]), "r"(a[2]), "r"(a[3]), "r"(b[0]), "r"(b[1]));
}

__device__ __forceinline__ uint32_t pack_h2(float x, float y)
{
    __half2 t = __floats2half2_rn(x, y);
    return *(uint32_t*)&t;
}

// ---------------- RMSNorm (+ optional RoPE) -> tiled fp16 ----------------
__global__ void __launch_bounds__(256) rms_rope_kernel(
    const float* __restrict__ x, const float* __restrict__ scale,
    __half* __restrict__ n_out, __half* __restrict__ r_out)
{
    const int row = blockIdx.x;
    const int tid = threadIdx.x;
    __shared__ float red[8];
    __shared__ float th[32];

    if (tid < 32)
        th[tid] = (float)exp(-((double)(2 * tid) / 64.0) * 9.210340371976184);

    float4 v = *(const float4*)(x + (size_t)row * DM + tid * 4);
    float ss = v.x * v.x + v.y * v.y + v.z * v.z + v.w * v.w;
    #pragma unroll
    for (int o = 16; o > 0; o >>= 1) ss += __shfl_xor_sync(0xffffffffu, ss, o);
    if ((tid & 31) == 0) red[tid >> 5] = ss;
    __syncthreads();
    float tot = 0.f;
    #pragma unroll
    for (int i = 0; i < 8; i++) tot += red[i];
    const float r = rsqrtf(tot * (1.0f / (float)DM) + 1e-6f);

    float4 sc = *(const float4*)(scale + tid * 4);
    float4 n;
    n.x = v.x * r * sc.x;
    n.y = v.y * r * sc.y;
    n.z = v.z * r * sc.z;
    n.w = v.w * r * sc.w;

    const int mt = row >> 7, rr = row & 127;
    const int c0 = tid * 4;
    const int kc = c0 >> 6, kk = c0 & 63;
    const size_t base = ((size_t)mt * (DM / 64) + kc) * TILE_ELEMS;
    const uint32_t off = sw128(rr * 128 + kk * 2) >> 1;
    n_out[base + off + 0] = __float2half_rn(n.x);
    n_out[base + off + 1] = __float2half_rn(n.y);
    n_out[base + off + 2] = __float2half_rn(n.z);
    n_out[base + off + 3] = __float2half_rn(n.w);

    if (r_out != nullptr) {
        const int t = row & (SEQ - 1);
        const int c = c0 & (HD - 1);
        const int p = c >> 1;
        float a0 = (float)t * th[p];
        float a1 = (float)t * th[p + 1];
        float s0, co0, s1, co1;
        sincosf(a0, &s0, &co0);
        sincosf(a1, &s1, &co1);
        r_out[base + off + 0] = __float2half_rn(n.x * co0 - n.y * s0);
        r_out[base + off + 1] = __float2half_rn(n.y * co0 + n.x * s0);
        r_out[base + off + 2] = __float2half_rn(n.z * co1 - n.w * s1);
        r_out[base + off + 3] = __float2half_rn(n.w * co1 + n.z * s1);
    }
}

// ---------------- fp32 [N,K] -> tiled fp16 -------------------------------
__global__ void __launch_bounds__(256) conv_tiled_kernel(
    const float* __restrict__ in, int K, __half* __restrict__ out)
{
    const int kc = blockIdx.x;
    const int rt = blockIdx.y;
    const int NCk = gridDim.x;
    const size_t base = ((size_t)rt * NCk + kc) * (size_t)TILE_ELEMS;
    for (int idx = threadIdx.x; idx < TILE_ELEMS; idx += 256) {
        const int r = idx >> 6, k = idx & 63;
        float v = in[(size_t)(rt * 128 + r) * K + kc * 64 + k];
        const uint32_t off = sw128(r * 128 + k * 2) >> 1;
        out[base + off] = __float2half_rn(v);
    }
}

// ---------------- mma.sync fp16 GEMM -------------------------------------
template <int ACT, int RES, int OUTT>
__global__ void __launch_bounds__(256) gemm_mma(
    const __half* __restrict__ A, const __half* __restrict__ B,
    const float* __restrict__ bias, const float* __restrict__ resid,
    float* __restrict__ C, __half* __restrict__ O,
    int N, int K)
{
    extern __shared__ char smem[];
    const uint32_t sbase = (smem_u32(smem) + 127) & ~127u;

    const int tid = threadIdx.x;
    const int lane = tid & 31, wid = tid >> 5;
    const int wm = wid >> 1, wn = wid & 1;
    const int NC = K >> 6;
    const int mt = blockIdx.y, nt = blockIdx.x;

    const uint32_t xr = (uint32_t)((lane & 7) << 4);
    uint32_t aRow[2];
    #pragma unroll
    for (int mi = 0; mi < 2; mi++)
        aRow[mi] = (uint32_t)((wm * 32 + mi * 16 + (lane & 15)) * 128);
    const uint32_t kA = (uint32_t)((lane >> 4) * 16);

    const int nb = wn * 64 + ((lane >> 4) << 3) + (lane & 7);
    uint32_t bRow[4];
    #pragma unroll
    for (int np = 0; np < 4; np++)
        bRow[np] = (uint32_t)((nb + np * 16) * 128);
    const uint32_t kB = (uint32_t)(((lane >> 3) & 1) * 16);

    float acc[2][8][4];
    #pragma unroll
    for (int mi = 0; mi < 2; mi++)
        #pragma unroll
        for (int nj = 0; nj < 8; nj++)
            #pragma unroll
            for (int q = 0; q < 4; q++) acc[mi][nj][q] = 0.f;

    auto load_chunk = [&](int i) {
        const uint32_t st = sbase + (uint32_t)(i & 1) * STAGE_BYTES;
        const char* ga = (const char*)(A + ((size_t)mt * NC + i) * TILE_ELEMS);
        const char* gb = (const char*)(B + ((size_t)nt * NC + i) * TILE_ELEMS);
        #pragma unroll 4
        for (int j = tid; j < 1024; j += 256) {
            cp16(st + j * 16,         ga + j * 16);
            cp16(st + 16384 + j * 16, gb + j * 16);
        }
        asm volatile("cp.async.commit_group;" ::: "memory");
    };

    load_chunk(0);
    for (int i = 0; i < NC; i++) {
        if (i + 1 < NC) {
            load_chunk(i + 1);
            asm volatile("cp.async.wait_group 1;" ::: "memory");
        } else {
            asm volatile("cp.async.wait_group 0;" ::: "memory");
        }
        __syncthreads();

        const uint32_t st = sbase + (uint32_t)(i & 1) * STAGE_BYTES;
        const uint32_t sA = st, sB = st + 16384;

        #pragma unroll
        for (int ks = 0; ks < 4; ks++) {
            const uint32_t ka = (uint32_t)(ks * 32) + kA;
            const uint32_t kb = (uint32_t)(ks * 32) + kB;
            uint32_t a[2][4], b[4][4];
            #pragma unroll
            for (int mi = 0; mi < 2; mi++)
                ldsm4(a[mi], sA + aRow[mi] + (ka ^ xr));
            #pragma unroll
            for (int np = 0; np < 4; np++)
                ldsm4(b[np], sB + bRow[np] + (kb ^ xr));
            #pragma unroll
            for (int mi = 0; mi < 2; mi++)
                #pragma unroll
                for (int nj = 0; nj < 8; nj++)
                    mma_f16(acc[mi][nj], a[mi], &b[nj >> 1][(nj & 1) * 2]);
        }
        __syncthreads();
    }

    const int m_base = mt * 128 + wm * 32 + (lane >> 2);
    const int n_base = nt * 128 + wn * 64 + (lane & 3) * 2;
    #pragma unroll
    for (int mi = 0; mi < 2; mi++) {
        #pragma unroll
        for (int nj = 0; nj < 8; nj++) {
            const int n = n_base + nj * 8;
            const float b0 = bias[n], b1 = bias[n + 1];
            float v00 = acc[mi][nj][0] + b0, v01 = acc[mi][nj][1] + b1;
            float v10 = acc[mi][nj][2] + b0, v11 = acc[mi][nj][3] + b1;
            if (ACT == 1) {
                v00 = v00 / (1.0f + fexp(-v00));
                v01 = v01 / (1.0f + fexp(-v01));
                v10 = v10 / (1.0f + fexp(-v10));
                v11 = v11 / (1.0f + fexp(-v11));
            }
            const int m0 = m_base + mi * 16, m1 = m0 + 8;
            if (OUTT == 1) {
                const int kc = n >> 6, kk = n & 63;
                const size_t tb = ((size_t)mt * (N >> 6) + kc) * TILE_ELEMS;
                const uint32_t o0 = sw128((m0 & 127) * 128 + kk * 2) >> 1;
                const uint32_t o1 = sw128((m1 & 127) * 128 + kk * 2) >> 1;
                O[tb + o0]     = __float2half_rn(v00);
                O[tb + o0 + 1] = __float2half_rn(v01);
                O[tb + o1]     = __float2half_rn(v10);
                O[tb + o1 + 1] = __float2half_rn(v11);
            } else {
                const size_t o0 = (size_t)m0 * N + n;
                const size_t o1 = (size_t)m1 * N + n;
                if (RES == 1) {
                    float2 r0 = *(const float2*)(resid + o0);
                    float2 r1 = *(const float2*)(resid + o1);
                    v00 += r0.x; v01 += r0.y; v10 += r1.x; v11 += r1.y;
                }
                *(float2*)(C + o0) = make_float2(v00, v01);
                *(float2*)(C + o1) = make_float2(v10, v11);
            }
        }
    }
}

// ---------------- tensor-core causal flash attention ---------------------
// grid (16 qtiles, 16 heads, 2 batch), 256 thr = 8 warps x 16 q-rows
__global__ void __launch_bounds__(256) flash_mma_kernel(
    const __half* __restrict__ Q, const __half* __restrict__ K,
    const __half* __restrict__ V, __half* __restrict__ Cc)
{
    extern __shared__ char smem[];
    const uint32_t sbase = smem_u32(smem);

    const int tid = threadIdx.x, lane = tid & 31, wq = tid >> 5;
    const int qt = 15 - blockIdx.x;           // big tiles first
    const int h = blockIdx.y, b = blockIdx.z;
    const int mtq = b * 16 + qt;
    const int KT = 2 * qt + 2;

    const uint32_t sQ = sbase;

    // Q tile async load
    {
        const char* gQ = (const char*)(Q + ((size_t)mtq * 16 + h) * TILE_ELEMS);
        for (int j = tid; j < 1024; j += 256)
            cp16(sQ + j * 16, gQ + j * 16);
        asm volatile("cp.async.commit_group;" ::: "memory");
    }

    auto load_kv = [&](int kt) {
        const uint32_t st = sbase + 16384 + (uint32_t)(kt & 1) * 16384;
        const int mtk = b * 16 + (kt >> 1);
        const size_t toff = ((size_t)mtk * 16 + h) * TILE_ELEMS + (size_t)(kt & 1) * 4096;
        const char* gk = (const char*)(K + toff);
        const char* gv = (const char*)(V + toff);
        for (int j = tid; j < 512; j += 256) {
            cp16(st + j * 16,        gk + j * 16);
            cp16(st + 8192 + j * 16, gv + j * 16);
        }
        asm volatile("cp.async.commit_group;" ::: "memory");
    };
    load_kv(0);
    asm volatile("cp.async.wait_group 0;" ::: "memory");
    __syncthreads();

    // Q A-fragments
    const uint32_t xr = (uint32_t)((lane & 7) << 4);
    const uint32_t aRow = (uint32_t)((wq * 16 + (lane & 15)) * 128);
    const uint32_t kA = (uint32_t)((lane >> 4) * 16);
    uint32_t qf[4][4];
    #pragma unroll
    for (int ks = 0; ks < 4; ks++)
        ldsm4(qf[ks], sQ + aRow + (((uint32_t)(ks * 32) + kA) ^ xr));

    float o[8][4];
    #pragma unroll
    for (int nj = 0; nj < 8; nj++)
        #pragma unroll
        for (int q = 0; q < 4; q++) o[nj][q] = 0.f;
    float m0 = -1e30f, m1 = -1e30f, l0 = 0.f, l1 = 0.f;

    const uint32_t nbK = (uint32_t)(((lane >> 4) << 3) + (lane & 7));
    const uint32_t kB = (uint32_t)(((lane >> 3) & 1) * 16);
    const int vmi = lane >> 3, vri = lane & 7;

    const int row_lo = qt * 128 + wq * 16;

    for (int kt = 0; kt < KT; kt++) {
        if (kt + 1 < KT) {
            load_kv(kt + 1);
            asm volatile("cp.async.wait_group 1;" ::: "memory");
        } else {
            asm volatile("cp.async.wait_group 0;" ::: "memory");
        }
        __syncthreads();

        if (kt * 64 <= row_lo + 15) {
            const uint32_t st = sbase + 16384 + (uint32_t)(kt & 1) * 16384;
            const uint32_t sK = st, sV = st + 8192;

            float S[8][4];
            #pragma unroll
            for (int nj = 0; nj < 8; nj++)
                #pragma unroll
                for (int q = 0; q < 4; q++) S[nj][q] = 0.f;

            #pragma unroll
            for (int ks = 0; ks < 4; ks++) {
                const uint32_t kb = (uint32_t)(ks * 32) + kB;
                uint32_t bk[4][4];
                #pragma unroll
                for (int np = 0; np < 4; np++)
                    ldsm4(bk[np], sK + (nbK + np * 16) * 128 + (kb ^ xr));
                #pragma unroll
                for (int nj = 0; nj < 8; nj++)
                    mma_f16(S[nj], qf[ks], &bk[nj >> 1][(nj & 1) * 2]);
            }

            const int r0 = row_lo + (lane >> 2);
            const bool need_mask = (kt * 64 + 63) > row_lo;
            #pragma unroll
            for (int nj = 0; nj < 8; nj++)
                #pragma unroll
                for (int q = 0; q < 4; q++) S[nj][q] *= 0.125f;
            if (need_mask) {
                #pragma unroll
                for (int nj = 0; nj < 8; nj++)
                    #pragma unroll
                    for (int q = 0; q < 4; q++) {
                        const int kg = kt * 64 + nj * 8 + (lane & 3) * 2 + (q & 1);
                        const int qg = r0 + ((q >= 2) ? 8 : 0);
                        if (kg > qg) S[nj][q] = -1e30f;
                    }
            }

            float t0 = -1e30f, t1 = -1e30f;
            #pragma unroll
            for (int nj = 0; nj < 8; nj++) {
                t0 = fmaxf(t0, fmaxf(S[nj][0], S[nj][1]));
                t1 = fmaxf(t1, fmaxf(S[nj][2], S[nj][3]));
            }
            t0 = fmaxf(t0, __shfl_xor_sync(0xffffffffu, t0, 1));
            t0 = fmaxf(t0, __shfl_xor_sync(0xffffffffu, t0, 2));
            t1 = fmaxf(t1, __shfl_xor_sync(0xffffffffu, t1, 1));
            t1 = fmaxf(t1, __shfl_xor_sync(0xffffffffu, t1, 2));
            const float mn0 = fmaxf(m0, t0), mn1 = fmaxf(m1, t1);
            const float c0 = fexp(m0 - mn0), c1 = fexp(m1 - mn1);
            m0 = mn0; m1 = mn1;
            l0 *= c0; l1 *= c1;
            #pragma unroll
            for (int nj = 0; nj < 8; nj++) {
                o[nj][0] *= c0; o[nj][1] *= c0;
                o[nj][2] *= c1; o[nj][3] *= c1;
            }
            float ls0 = 0.f, ls1 = 0.f;
            #pragma unroll
            for (int nj = 0; nj < 8; nj++) {
                S[nj][0] = fexp(S[nj][0] - mn0); ls0 += S[nj][0];
                S[nj][1] = fexp(S[nj][1] - mn0); ls0 += S[nj][1];
                S[nj][2] = fexp(S[nj][2] - mn1); ls1 += S[nj][2];
                S[nj][3] = fexp(S[nj][3] - mn1); ls1 += S[nj][3];
            }
            l0 += ls0; l1 += ls1;

            // P @ V (V via ldmatrix.trans)
            #pragma unroll
            for (int kk = 0; kk < 4; kk++) {
                uint32_t ap[4];
                ap[0] = pack_h2(S[2*kk][0],   S[2*kk][1]);
                ap[1] = pack_h2(S[2*kk][2],   S[2*kk][3]);
                ap[2] = pack_h2(S[2*kk+1][0], S[2*kk+1][1]);
                ap[3] = pack_h2(S[2*kk+1][2], S[2*kk+1][3]);
                uint32_t vf[4][4];
                const uint32_t vrow = (uint32_t)(kk * 16 + (vmi & 1) * 8 + vri);
                #pragma unroll
                for (int g = 0; g < 4; g++) {
                    const uint32_t off = sw128(vrow * 128 + (uint32_t)(g * 16 + (vmi >> 1) * 8) * 2);
                    ldsm4t(vf[g], sV + off);
                }
                #pragma unroll
                for (int nj = 0; nj < 8; nj++)
                    mma_f16(o[nj], ap, &vf[nj >> 1][(nj & 1) * 2]);
            }
        }
        __syncthreads();
    }

    l0 += __shfl_xor_sync(0xffffffffu, l0, 1);
    l0 += __shfl_xor_sync(0xffffffffu, l0, 2);
    l1 += __shfl_xor_sync(0xffffffffu, l1, 1);
    l1 += __shfl_xor_sync(0xffffffffu, l1, 2);
    const float inv0 = 1.0f / l0, inv1 = 1.0f / l1;

    const size_t tb = ((size_t)mtq * 16 + h) * TILE_ELEMS;
    const int rl0 = wq * 16 + (lane >> 2), rl1 = rl0 + 8;
    #pragma unroll
    for (int nj = 0; nj < 8; nj++) {
        const int col = nj * 8 + (lane & 3) * 2;
        const uint32_t o0 = sw128(rl0 * 128 + col * 2) >> 1;
        const uint32_t o1 = sw128(rl1 * 128 + col * 2) >> 1;
        Cc[tb + o0]     = __float2half_rn(o[nj][0] * inv0);
        Cc[tb + o0 + 1] = __float2half_rn(o[nj][1] * inv0);
        Cc[tb + o1]     = __float2half_rn(o[nj][2] * inv1);
        Cc[tb + o1 + 1] = __float2half_rn(o[nj][3] * inv1);
    }
}

// ---------------- launch -------------------------------------------------
#define SYMADDR(p, s) cudaGetSymbolAddress((void**)&(p), s)

extern "C" void kernel_launch(void* const* d_in, const int* in_sizes, int n_in,
                              void* d_out, int out_size)
{
    const float* x         = (const float*)d_in[0];
    const float* rms_scale = (const float*)d_in[1];
    const float* in_proj_w = (const float*)d_in[2];
    const float* in_proj_b = (const float*)d_in[3];
    const float* out_proj_w= (const float*)d_in[4];
    const float* out_proj_b= (const float*)d_in[5];
    const float* w1        = (const float*)d_in[6];
    const float* b1        = (const float*)d_in[7];
    const float* w2        = (const float*)d_in[8];
    const float* b2        = (const float*)d_in[9];
    float* out = (float*)d_out;

    float *p_y;
    __half *xr, *xn, *q, *k, *v, *ctx, *yn, *hh;
    __half *wqk, *wv, *wo, *w1h, *w2h;
    SYMADDR(p_y, g_y);
    SYMADDR(xr, t_xr);   SYMADDR(xn, t_xn);
    SYMADDR(q, t_q);     SYMADDR(k, t_k);    SYMADDR(v, t_v);
    SYMADDR(ctx, t_ctx); SYMADDR(yn, t_yn);  SYMADDR(hh, t_h);
    SYMADDR(wqk, t_wqk); SYMADDR(wv, t_wv);  SYMADDR(wo, t_wo);
    SYMADDR(w1h, t_w1);  SYMADDR(w2h, t_w2);

    cudaFuncSetAttribute(gemm_mma<0,0,0>, cudaFuncAttributeMaxDynamicSharedMemorySize, GEMM_SMEM);
    cudaFuncSetAttribute(gemm_mma<0,0,1>, cudaFuncAttributeMaxDynamicSharedMemorySize, GEMM_SMEM);
    cudaFuncSetAttribute(gemm_mma<1,0,1>, cudaFuncAttributeMaxDynamicSharedMemorySize, GEMM_SMEM);
    cudaFuncSetAttribute(gemm_mma<0,1,0>, cudaFuncAttributeMaxDynamicSharedMemorySize, GEMM_SMEM);
    cudaFuncSetAttribute(flash_mma_kernel, cudaFuncAttributeMaxDynamicSharedMemorySize, ATTN_SMEM);

    // weight conversions -> tiled fp16
    conv_tiled_kernel<<<dim3(16, 16), 256>>>(in_proj_w,                     DM, wqk);
    conv_tiled_kernel<<<dim3(16, 8),  256>>>(in_proj_w + (size_t)2048 * DM, DM, wv);
    conv_tiled_kernel<<<dim3(16, 8),  256>>>(out_proj_w,                    DM, wo);
    conv_tiled_kernel<<<dim3(16, 32), 256>>>(w1,                            DM, w1h);
    conv_tiled_kernel<<<dim3(64, 8),  256>>>(w2,                            FF, w2h);

    // 1) xn = rmsnorm(x); xr = rope(xn)
    rms_rope_kernel<<<MROWS, 256>>>(x, rms_scale, xn, xr);

    // 2) q/k/v projections -> attention tiles (mt, head)
    gemm_mma<0,0,1><<<dim3(8, 32), 256, GEMM_SMEM>>>(
        xr, wqk, in_proj_b, nullptr, nullptr, q, DM, DM);
    gemm_mma<0,0,1><<<dim3(8, 32), 256, GEMM_SMEM>>>(
        xr, wqk + (size_t)1024 * DM, in_proj_b + DM, nullptr, nullptr, k, DM, DM);
    gemm_mma<0,0,1><<<dim3(8, 32), 256, GEMM_SMEM>>>(
        xn, wv, in_proj_b + 2 * DM, nullptr, nullptr, v, DM, DM);

    // 3) tensor-core causal attention -> ctx tiles
    flash_mma_kernel<<<dim3(16, NH, BATCH), 256, ATTN_SMEM>>>(q, k, v, ctx);

    // 4) y = ctx @ Wo^T + b
    gemm_mma<0,0,0><<<dim3(8, 32), 256, GEMM_SMEM>>>(
        ctx, wo, out_proj_b, nullptr, p_y, nullptr, DM, DM);

    // 5) yn = rmsnorm(y)
    rms_rope_kernel<<<MROWS, 256>>>(p_y, rms_scale, yn, nullptr);

    // 6) h = silu(yn @ w1^T + b1) -> tiled fp16
    gemm_mma<1,0,1><<<dim3(32, 32), 256, GEMM_SMEM>>>(
        yn, w1h, b1, nullptr, nullptr, hh, FF, DM);

    // 7) out = y + (h @ w2^T + b2)
    gemm_mma<0,1,0><<<dim3(8, 32), 256, GEMM_SMEM>>>(
        hh, w2h, b2, p_y, out, nullptr, DM, FF);
}

// round 6
// speedup vs baseline: 7.3900x; 1.1384x over previous
#include <cuda_runtime.h>
#include <cuda_fp16.h>
#include <cstdint>
#include <math.h>

// Problem constants
#define BATCH 2
#define SEQ   2048
#define DM    1024
#define NH    16
#define HD    64
#define FF    4096
#define MROWS (BATCH * SEQ)   // 4096

#define TILE_ELEMS 8192                 // 128 rows x 64 fp16 (SW128)
#define TILE_BYTES 16384
#define STAGE_BYTES 32768               // A tile + B tile
#define NSTAGE 3
#define GEMM_SMEM   (NSTAGE * STAGE_BYTES + 256)
#define ATTN_SMEM   (16384 + 2 * 16384) // Q + 2 KV stages

// ---------------- scratch -----------------------------------------------
__device__ float g_y  [MROWS * DM];

__device__ __half t_xr [MROWS * DM];
__device__ __half t_xn [MROWS * DM];
__device__ __half t_q  [MROWS * DM];
__device__ __half t_k  [MROWS * DM];
__device__ __half t_v  [MROWS * DM];
__device__ __half t_ctx[MROWS * DM];
__device__ __half t_yn [MROWS * DM];
__device__ __half t_h  [MROWS * FF];
__device__ __half t_wqk[2048 * DM];
__device__ __half t_wv [DM * DM];
__device__ __half t_wo [DM * DM];
__device__ __half t_w1 [FF * DM];
__device__ __half t_w2 [DM * FF];

// ---------------- helpers -----------------------------------------------
__device__ __forceinline__ uint32_t sw128(uint32_t o) { return o ^ ((o >> 3) & 0x70); }

__device__ __forceinline__ float fexp(float x)
{
    x = fminf(fmaxf(x, -87.f), 87.f);
    float y = x * 1.4426950408889634f;
    float r = rintf(y);
    float f = y - r;
    float p = 1.33336498e-3f;
    p = fmaf(p, f, 9.61793571e-3f);
    p = fmaf(p, f, 5.55043442e-2f);
    p = fmaf(p, f, 2.40226507e-1f);
    p = fmaf(p, f, 6.93147182e-1f);
    p = fmaf(p, f, 1.0f);
    return p * __int_as_float(((int)r + 127) << 23);
}

__device__ __forceinline__ uint32_t smem_u32(const void* p)
{
    uint32_t a;
    asm("{ .reg .u64 t; cvta.to.shared.u64 t, %1; cvt.u32.u64 %0, t; }" : "=r"(a) : "l"(p));
    return a;
}

__device__ __forceinline__ void cp16(uint32_t s, const void* g)
{
    asm volatile("cp.async.cg.shared.global [%0], [%1], 16;" :: "r"(s), "l"(g));
}

__device__ __forceinline__ void ldsm4(uint32_t* r, uint32_t addr)
{
    asm volatile("ldmatrix.sync.aligned.m8n8.x4.shared.b16 {%0,%1,%2,%3}, [%4];"
                 : "=r"(r[0]), "=r"(r[1]), "=r"(r[2]), "=r"(r[3]) : "r"(addr));
}

__device__ __forceinline__ void ldsm4t(uint32_t* r, uint32_t addr)
{
    asm volatile("ldmatrix.sync.aligned.m8n8.x4.trans.shared.b16 {%0,%1,%2,%3}, [%4];"
                 : "=r"(r[0]), "=r"(r[1]), "=r"(r[2]), "=r"(r[3]) : "r"(addr));
}

__device__ __forceinline__ void mma_f16(float* d, const uint32_t* a, const uint32_t* b)
{
    asm volatile(
        "mma.sync.aligned.m16n8k16.row.col.f32.f16.f16.f32 "
        "{%0,%1,%2,%3}, {%4,%5,%6,%7}, {%8,%9}, {%0,%1,%2,%3};"
        : "+f"(d[0]), "+f"(d[1]), "+f"(d[2]), "+f"(d[3])
        : "r"(a[0]), "r"(a[1]), "r"(a[2]), "r"(a[3]), "r"(b[0]), "r"(b[1]));
}

__device__ __forceinline__ uint32_t pack_h2(float x, float y)
{
    __half2 t = __floats2half2_rn(x, y);
    return *(uint32_t*)&t;
}

// ---------------- RMSNorm (+ optional RoPE) -> tiled fp16 ----------------
__global__ void __launch_bounds__(256) rms_rope_kernel(
    const float* __restrict__ x, const float* __restrict__ scale,
    __half* __restrict__ n_out, __half* __restrict__ r_out)
{
    const int row = blockIdx.x;
    const int tid = threadIdx.x;
    __shared__ float red[8];
    __shared__ float th[32];

    if (tid < 32)
        th[tid] = (float)exp(-((double)(2 * tid) / 64.0) * 9.210340371976184);

    float4 v = *(const float4*)(x + (size_t)row * DM + tid * 4);
    float ss = v.x * v.x + v.y * v.y + v.z * v.z + v.w * v.w;
    #pragma unroll
    for (int o = 16; o > 0; o >>= 1) ss += __shfl_xor_sync(0xffffffffu, ss, o);
    if ((tid & 31) == 0) red[tid >> 5] = ss;
    __syncthreads();
    float tot = 0.f;
    #pragma unroll
    for (int i = 0; i < 8; i++) tot += red[i];
    const float r = rsqrtf(tot * (1.0f / (float)DM) + 1e-6f);

    float4 sc = *(const float4*)(scale + tid * 4);
    float4 n;
    n.x = v.x * r * sc.x;
    n.y = v.y * r * sc.y;
    n.z = v.z * r * sc.z;
    n.w = v.w * r * sc.w;

    const int mt = row >> 7, rr = row & 127;
    const int c0 = tid * 4;
    const int kc = c0 >> 6, kk = c0 & 63;
    const size_t base = ((size_t)mt * (DM / 64) + kc) * TILE_ELEMS;
    const uint32_t off = sw128(rr * 128 + kk * 2) >> 1;
    {
        uint2 pk;
        pk.x = pack_h2(n.x, n.y);
        pk.y = pack_h2(n.z, n.w);
        *(uint2*)(n_out + base + off) = pk;
    }

    if (r_out != nullptr) {
        const int t = row & (SEQ - 1);
        const int c = c0 & (HD - 1);
        const int p = c >> 1;
        float a0 = (float)t * th[p];
        float a1 = (float)t * th[p + 1];
        float s0, co0, s1, co1;
        sincosf(a0, &s0, &co0);
        sincosf(a1, &s1, &co1);
        uint2 pk;
        pk.x = pack_h2(n.x * co0 - n.y * s0, n.y * co0 + n.x * s0);
        pk.y = pack_h2(n.z * co1 - n.w * s1, n.w * co1 + n.z * s1);
        *(uint2*)(r_out + base + off) = pk;
    }
}

// ---------------- fp32 [N,K] -> tiled fp16 (vectorized) ------------------
__global__ void __launch_bounds__(256) conv_tiled_kernel(
    const float* __restrict__ in, int K, __half* __restrict__ out)
{
    const int kc = blockIdx.x;
    const int rt = blockIdx.y;
    const int NCk = gridDim.x;
    const size_t base = ((size_t)rt * NCk + kc) * (size_t)TILE_ELEMS;
    #pragma unroll
    for (int idx = threadIdx.x; idx < 1024; idx += 256) {
        const int r = idx >> 3, k = (idx & 7) * 8;
        const float* gp = in + (size_t)(rt * 128 + r) * K + kc * 64 + k;
        const float4 a = *(const float4*)gp;
        const float4 b = *(const float4*)(gp + 4);
        uint4 pk;
        pk.x = pack_h2(a.x, a.y);
        pk.y = pack_h2(a.z, a.w);
        pk.z = pack_h2(b.x, b.y);
        pk.w = pack_h2(b.z, b.w);
        const uint32_t off = sw128(r * 128 + k * 2) >> 1;
        *(uint4*)(out + base + off) = pk;
    }
}

// ---------------- mma.sync fp16 GEMM (3-stage pipeline) ------------------
// OUTT: 0 = fp32 row-major C (optional residual), 1 = fp16 tiled O,
//       2 = fp16 tiled split: n<1024 -> O, n>=1024 -> O2
template <int ACT, int RES, int OUTT>
__global__ void __launch_bounds__(256) gemm_mma(
    const __half* __restrict__ A, const __half* __restrict__ B,
    const float* __restrict__ bias, const float* __restrict__ resid,
    float* __restrict__ C, __half* __restrict__ O, __half* __restrict__ O2,
    int N, int K)
{
    extern __shared__ char smem[];
    const uint32_t sbase = (smem_u32(smem) + 127) & ~127u;

    const int tid = threadIdx.x;
    const int lane = tid & 31, wid = tid >> 5;
    const int wm = wid >> 1, wn = wid & 1;
    const int NC = K >> 6;
    const int mt = blockIdx.y, nt = blockIdx.x;

    const uint32_t xr = (uint32_t)((lane & 7) << 4);
    uint32_t aRow[2];
    #pragma unroll
    for (int mi = 0; mi < 2; mi++)
        aRow[mi] = (uint32_t)((wm * 32 + mi * 16 + (lane & 15)) * 128);
    const uint32_t kA = (uint32_t)((lane >> 4) * 16);

    const int nb = wn * 64 + ((lane >> 4) << 3) + (lane & 7);
    uint32_t bRow[4];
    #pragma unroll
    for (int np = 0; np < 4; np++)
        bRow[np] = (uint32_t)((nb + np * 16) * 128);
    const uint32_t kB = (uint32_t)(((lane >> 3) & 1) * 16);

    float acc[2][8][4];
    #pragma unroll
    for (int mi = 0; mi < 2; mi++)
        #pragma unroll
        for (int nj = 0; nj < 8; nj++)
            #pragma unroll
            for (int q = 0; q < 4; q++) acc[mi][nj][q] = 0.f;

    auto load_chunk = [&](int i) {
        const uint32_t st = sbase + (uint32_t)(i % NSTAGE) * STAGE_BYTES;
        const char* ga = (const char*)(A + ((size_t)mt * NC + i) * TILE_ELEMS);
        const char* gb = (const char*)(B + ((size_t)nt * NC + i) * TILE_ELEMS);
        #pragma unroll 4
        for (int j = tid; j < 1024; j += 256) {
            cp16(st + j * 16,         ga + j * 16);
            cp16(st + 16384 + j * 16, gb + j * 16);
        }
        asm volatile("cp.async.commit_group;" ::: "memory");
    };

    load_chunk(0);
    if (NC > 1) load_chunk(1);
    for (int i = 0; i < NC; i++) {
        if (i < NC - 1) asm volatile("cp.async.wait_group 1;" ::: "memory");
        else            asm volatile("cp.async.wait_group 0;" ::: "memory");
        __syncthreads();
        if (i + 2 < NC) load_chunk(i + 2);

        const uint32_t st = sbase + (uint32_t)(i % NSTAGE) * STAGE_BYTES;
        const uint32_t sA = st, sB = st + 16384;

        #pragma unroll
        for (int ks = 0; ks < 4; ks++) {
            const uint32_t ka = (uint32_t)(ks * 32) + kA;
            const uint32_t kb = (uint32_t)(ks * 32) + kB;
            uint32_t a[2][4], b[4][4];
            #pragma unroll
            for (int mi = 0; mi < 2; mi++)
                ldsm4(a[mi], sA + aRow[mi] + (ka ^ xr));
            #pragma unroll
            for (int np = 0; np < 4; np++)
                ldsm4(b[np], sB + bRow[np] + (kb ^ xr));
            #pragma unroll
            for (int mi = 0; mi < 2; mi++)
                #pragma unroll
                for (int nj = 0; nj < 8; nj++)
                    mma_f16(acc[mi][nj], a[mi], &b[nj >> 1][(nj & 1) * 2]);
        }
        __syncthreads();
    }

    const int m_base = mt * 128 + wm * 32 + (lane >> 2);
    const int n_base = nt * 128 + wn * 64 + (lane & 3) * 2;
    #pragma unroll
    for (int mi = 0; mi < 2; mi++) {
        #pragma unroll
        for (int nj = 0; nj < 8; nj++) {
            const int n = n_base + nj * 8;
            const float b0 = bias[n], b1 = bias[n + 1];
            float v00 = acc[mi][nj][0] + b0, v01 = acc[mi][nj][1] + b1;
            float v10 = acc[mi][nj][2] + b0, v11 = acc[mi][nj][3] + b1;
            if (ACT == 1) {
                v00 = v00 / (1.0f + fexp(-v00));
                v01 = v01 / (1.0f + fexp(-v01));
                v10 = v10 / (1.0f + fexp(-v10));
                v11 = v11 / (1.0f + fexp(-v11));
            }
            const int m0 = m_base + mi * 16, m1 = m0 + 8;
            if (OUTT >= 1) {
                int kc = n >> 6;
                __half* Od = O;
                int ntiles = N >> 6;
                if (OUTT == 2) {
                    ntiles = 16;
                    if (kc >= 16) { Od = O2; kc -= 16; }
                }
                const int kk = n & 63;
                const size_t tb = ((size_t)mt * ntiles + kc) * TILE_ELEMS;
                const uint32_t o0 = sw128((m0 & 127) * 128 + kk * 2) >> 1;
                const uint32_t o1 = sw128((m1 & 127) * 128 + kk * 2) >> 1;
                *(uint32_t*)(Od + tb + o0) = pack_h2(v00, v01);
                *(uint32_t*)(Od + tb + o1) = pack_h2(v10, v11);
            } else {
                const size_t o0 = (size_t)m0 * N + n;
                const size_t o1 = (size_t)m1 * N + n;
                if (RES == 1) {
                    float2 r0 = *(const float2*)(resid + o0);
                    float2 r1 = *(const float2*)(resid + o1);
                    v00 += r0.x; v01 += r0.y; v10 += r1.x; v11 += r1.y;
                }
                *(float2*)(C + o0) = make_float2(v00, v01);
                *(float2*)(C + o1) = make_float2(v10, v11);
            }
        }
    }
}

// ---------------- tensor-core causal flash attention ---------------------
// grid (16 qtiles, 16 heads, 2 batch), 256 thr = 8 warps x 16 q-rows
__global__ void __launch_bounds__(256) flash_mma_kernel(
    const __half* __restrict__ Q, const __half* __restrict__ K,
    const __half* __restrict__ V, __half* __restrict__ Cc)
{
    extern __shared__ char smem[];
    const uint32_t sbase = smem_u32(smem);

    const int tid = threadIdx.x, lane = tid & 31, wq = tid >> 5;
    const int qt = 15 - blockIdx.x;           // big tiles first
    const int h = blockIdx.y, b = blockIdx.z;
    const int mtq = b * 16 + qt;
    const int KT = 2 * qt + 2;

    const uint32_t sQ = sbase;

    // Q tile async load
    {
        const char* gQ = (const char*)(Q + ((size_t)mtq * 16 + h) * TILE_ELEMS);
        for (int j = tid; j < 1024; j += 256)
            cp16(sQ + j * 16, gQ + j * 16);
        asm volatile("cp.async.commit_group;" ::: "memory");
    }

    auto load_kv = [&](int kt) {
        const uint32_t st = sbase + 16384 + (uint32_t)(kt & 1) * 16384;
        const int mtk = b * 16 + (kt >> 1);
        const size_t toff = ((size_t)mtk * 16 + h) * TILE_ELEMS + (size_t)(kt & 1) * 4096;
        const char* gk = (const char*)(K + toff);
        const char* gv = (const char*)(V + toff);
        for (int j = tid; j < 512; j += 256) {
            cp16(st + j * 16,        gk + j * 16);
            cp16(st + 8192 + j * 16, gv + j * 16);
        }
        asm volatile("cp.async.commit_group;" ::: "memory");
    };
    load_kv(0);
    asm volatile("cp.async.wait_group 0;" ::: "memory");
    __syncthreads();

    // Q A-fragments
    const uint32_t xr = (uint32_t)((lane & 7) << 4);
    const uint32_t aRow = (uint32_t)((wq * 16 + (lane & 15)) * 128);
    const uint32_t kA = (uint32_t)((lane >> 4) * 16);
    uint32_t qf[4][4];
    #pragma unroll
    for (int ks = 0; ks < 4; ks++)
        ldsm4(qf[ks], sQ + aRow + (((uint32_t)(ks * 32) + kA) ^ xr));

    float o[8][4];
    #pragma unroll
    for (int nj = 0; nj < 8; nj++)
        #pragma unroll
        for (int q = 0; q < 4; q++) o[nj][q] = 0.f;
    float m0 = -1e30f, m1 = -1e30f, l0 = 0.f, l1 = 0.f;

    const uint32_t nbK = (uint32_t)(((lane >> 4) << 3) + (lane & 7));
    const uint32_t kB = (uint32_t)(((lane >> 3) & 1) * 16);
    const int vmi = lane >> 3, vri = lane & 7;

    const int row_lo = qt * 128 + wq * 16;

    for (int kt = 0; kt < KT; kt++) {
        if (kt + 1 < KT) {
            load_kv(kt + 1);
            asm volatile("cp.async.wait_group 1;" ::: "memory");
        } else {
            asm volatile("cp.async.wait_group 0;" ::: "memory");
        }
        __syncthreads();

        if (kt * 64 <= row_lo + 15) {
            const uint32_t st = sbase + 16384 + (uint32_t)(kt & 1) * 16384;
            const uint32_t sK = st, sV = st + 8192;

            float S[8][4];
            #pragma unroll
            for (int nj = 0; nj < 8; nj++)
                #pragma unroll
                for (int q = 0; q < 4; q++) S[nj][q] = 0.f;

            #pragma unroll
            for (int ks = 0; ks < 4; ks++) {
                const uint32_t kb = (uint32_t)(ks * 32) + kB;
                uint32_t bk[4][4];
                #pragma unroll
                for (int np = 0; np < 4; np++)
                    ldsm4(bk[np], sK + (nbK + np * 16) * 128 + (kb ^ xr));
                #pragma unroll
                for (int nj = 0; nj < 8; nj++)
                    mma_f16(S[nj], qf[ks], &bk[nj >> 1][(nj & 1) * 2]);
            }

            const int r0 = row_lo + (lane >> 2);
            const bool need_mask = (kt * 64 + 63) > row_lo;
            #pragma unroll
            for (int nj = 0; nj < 8; nj++)
                #pragma unroll
                for (int q = 0; q < 4; q++) S[nj][q] *= 0.125f;
            if (need_mask) {
                #pragma unroll
                for (int nj = 0; nj < 8; nj++)
                    #pragma unroll
                    for (int q = 0; q < 4; q++) {
                        const int kg = kt * 64 + nj * 8 + (lane & 3) * 2 + (q & 1);
                        const int qg = r0 + ((q >= 2) ? 8 : 0);
                        if (kg > qg) S[nj][q] = -1e30f;
                    }
            }

            float t0 = -1e30f, t1 = -1e30f;
            #pragma unroll
            for (int nj = 0; nj < 8; nj++) {
                t0 = fmaxf(t0, fmaxf(S[nj][0], S[nj][1]));
                t1 = fmaxf(t1, fmaxf(S[nj][2], S[nj][3]));
            }
            t0 = fmaxf(t0, __shfl_xor_sync(0xffffffffu, t0, 1));
            t0 = fmaxf(t0, __shfl_xor_sync(0xffffffffu, t0, 2));
            t1 = fmaxf(t1, __shfl_xor_sync(0xffffffffu, t1, 1));
            t1 = fmaxf(t1, __shfl_xor_sync(0xffffffffu, t1, 2));
            const float mn0 = fmaxf(m0, t0), mn1 = fmaxf(m1, t1);
            const float c0 = fexp(m0 - mn0), c1 = fexp(m1 - mn1);
            m0 = mn0; m1 = mn1;
            l0 *= c0; l1 *= c1;
            #pragma unroll
            for (int nj = 0; nj < 8; nj++) {
                o[nj][0] *= c0; o[nj][1] *= c0;
                o[nj][2] *= c1; o[nj][3] *= c1;
            }
            float ls0 = 0.f, ls1 = 0.f;
            #pragma unroll
            for (int nj = 0; nj < 8; nj++) {
                S[nj][0] = fexp(S[nj][0] - mn0); ls0 += S[nj][0];
                S[nj][1] = fexp(S[nj][1] - mn0); ls0 += S[nj][1];
                S[nj][2] = fexp(S[nj][2] - mn1); ls1 += S[nj][2];
                S[nj][3] = fexp(S[nj][3] - mn1); ls1 += S[nj][3];
            }
            l0 += ls0; l1 += ls1;

            // P @ V (V via ldmatrix.trans)
            #pragma unroll
            for (int kk = 0; kk < 4; kk++) {
                uint32_t ap[4];
                ap[0] = pack_h2(S[2*kk][0],   S[2*kk][1]);
                ap[1] = pack_h2(S[2*kk][2],   S[2*kk][3]);
                ap[2] = pack_h2(S[2*kk+1][0], S[2*kk+1][1]);
                ap[3] = pack_h2(S[2*kk+1][2], S[2*kk+1][3]);
                uint32_t vf[4][4];
                const uint32_t vrow = (uint32_t)(kk * 16 + (vmi & 1) * 8 + vri);
                #pragma unroll
                for (int g = 0; g < 4; g++) {
                    const uint32_t off = sw128(vrow * 128 + (uint32_t)(g * 16 + (vmi >> 1) * 8) * 2);
                    ldsm4t(vf[g], sV + off);
                }
                #pragma unroll
                for (int nj = 0; nj < 8; nj++)
                    mma_f16(o[nj], ap, &vf[nj >> 1][(nj & 1) * 2]);
            }
        }
        __syncthreads();
    }

    l0 += __shfl_xor_sync(0xffffffffu, l0, 1);
    l0 += __shfl_xor_sync(0xffffffffu, l0, 2);
    l1 += __shfl_xor_sync(0xffffffffu, l1, 1);
    l1 += __shfl_xor_sync(0xffffffffu, l1, 2);
    const float inv0 = 1.0f / l0, inv1 = 1.0f / l1;

    const size_t tb = ((size_t)mtq * 16 + h) * TILE_ELEMS;
    const int rl0 = wq * 16 + (lane >> 2), rl1 = rl0 + 8;
    #pragma unroll
    for (int nj = 0; nj < 8; nj++) {
        const int col = nj * 8 + (lane & 3) * 2;
        const uint32_t o0 = sw128(rl0 * 128 + col * 2) >> 1;
        const uint32_t o1 = sw128(rl1 * 128 + col * 2) >> 1;
        *(uint32_t*)(Cc + tb + o0) = pack_h2(o[nj][0] * inv0, o[nj][1] * inv0);
        *(uint32_t*)(Cc + tb + o1) = pack_h2(o[nj][2] * inv1, o[nj][3] * inv1);
    }
}

// ---------------- launch -------------------------------------------------
#define SYMADDR(p, s) cudaGetSymbolAddress((void**)&(p), s)

extern "C" void kernel_launch(void* const* d_in, const int* in_sizes, int n_in,
                              void* d_out, int out_size)
{
    const float* x         = (const float*)d_in[0];
    const float* rms_scale = (const float*)d_in[1];
    const float* in_proj_w = (const float*)d_in[2];
    const float* in_proj_b = (const float*)d_in[3];
    const float* out_proj_w= (const float*)d_in[4];
    const float* out_proj_b= (const float*)d_in[5];
    const float* w1        = (const float*)d_in[6];
    const float* b1        = (const float*)d_in[7];
    const float* w2        = (const float*)d_in[8];
    const float* b2        = (const float*)d_in[9];
    float* out = (float*)d_out;

    float *p_y;
    __half *xr, *xn, *q, *k, *v, *ctx, *yn, *hh;
    __half *wqk, *wv, *wo, *w1h, *w2h;
    SYMADDR(p_y, g_y);
    SYMADDR(xr, t_xr);   SYMADDR(xn, t_xn);
    SYMADDR(q, t_q);     SYMADDR(k, t_k);    SYMADDR(v, t_v);
    SYMADDR(ctx, t_ctx); SYMADDR(yn, t_yn);  SYMADDR(hh, t_h);
    SYMADDR(wqk, t_wqk); SYMADDR(wv, t_wv);  SYMADDR(wo, t_wo);
    SYMADDR(w1h, t_w1);  SYMADDR(w2h, t_w2);

    cudaFuncSetAttribute(gemm_mma<0,0,0>, cudaFuncAttributeMaxDynamicSharedMemorySize, GEMM_SMEM);
    cudaFuncSetAttribute(gemm_mma<0,0,1>, cudaFuncAttributeMaxDynamicSharedMemorySize, GEMM_SMEM);
    cudaFuncSetAttribute(gemm_mma<0,0,2>, cudaFuncAttributeMaxDynamicSharedMemorySize, GEMM_SMEM);
    cudaFuncSetAttribute(gemm_mma<1,0,1>, cudaFuncAttributeMaxDynamicSharedMemorySize, GEMM_SMEM);
    cudaFuncSetAttribute(gemm_mma<0,1,0>, cudaFuncAttributeMaxDynamicSharedMemorySize, GEMM_SMEM);
    cudaFuncSetAttribute(flash_mma_kernel, cudaFuncAttributeMaxDynamicSharedMemorySize, ATTN_SMEM);

    // weight conversions -> tiled fp16
    conv_tiled_kernel<<<dim3(16, 16), 256>>>(in_proj_w,                     DM, wqk);
    conv_tiled_kernel<<<dim3(16, 8),  256>>>(in_proj_w + (size_t)2048 * DM, DM, wv);
    conv_tiled_kernel<<<dim3(16, 8),  256>>>(out_proj_w,                    DM, wo);
    conv_tiled_kernel<<<dim3(16, 32), 256>>>(w1,                            DM, w1h);
    conv_tiled_kernel<<<dim3(64, 8),  256>>>(w2,                            FF, w2h);

    // 1) xn = rmsnorm(x); xr = rope(xn)
    rms_rope_kernel<<<MROWS, 256>>>(x, rms_scale, xn, xr);

    // 2) [q|k] = xr @ [Wq;Wk]^T + b (N=2048, split outputs), v = xn @ Wv^T
    gemm_mma<0,0,2><<<dim3(16, 32), 256, GEMM_SMEM>>>(
        xr, wqk, in_proj_b, nullptr, nullptr, q, k, 2 * DM, DM);
    gemm_mma<0,0,1><<<dim3(8, 32), 256, GEMM_SMEM>>>(
        xn, wv, in_proj_b + 2 * DM, nullptr, nullptr, v, nullptr, DM, DM);

    // 3) tensor-core causal attention -> ctx tiles
    flash_mma_kernel<<<dim3(16, NH, BATCH), 256, ATTN_SMEM>>>(q, k, v, ctx);

    // 4) y = ctx @ Wo^T + b
    gemm_mma<0,0,0><<<dim3(8, 32), 256, GEMM_SMEM>>>(
        ctx, wo, out_proj_b, nullptr, p_y, nullptr, nullptr, DM, DM);

    // 5) yn = rmsnorm(y)
    rms_rope_kernel<<<MROWS, 256>>>(p_y, rms_scale, yn, nullptr);

    // 6) h = silu(yn @ w1^T + b1) -> tiled fp16
    gemm_mma<1,0,1><<<dim3(32, 32), 256, GEMM_SMEM>>>(
        yn, w1h, b1, nullptr, nullptr, hh, nullptr, FF, DM);

    // 7) out = y + (h @ w2^T + b2)
    gemm_mma<0,1,0><<<dim3(8, 32), 256, GEMM_SMEM>>>(
        hh, w2h, b2, p_y, out, nullptr, nullptr, DM, FF);
}

// round 7
// speedup vs baseline: 7.4320x; 1.0057x over previous
#include <cuda_runtime.h>
#include <cuda_fp16.h>
#include <cstdint>
#include <math.h>

// Problem constants
#define BATCH 2
#define SEQ   2048
#define DM    1024
#define NH    16
#define HD    64
#define FF    4096
#define MROWS (BATCH * SEQ)   // 4096

#define TILE_ELEMS 8192                 // 128 rows x 64 fp16 (SW128)
#define TILE_BYTES 16384
#define STAGE_BYTES 32768               // A tile + B tile
#define NSTAGE 3
#define GEMM_SMEM   (NSTAGE * STAGE_BYTES + 256)
#define ATTN_SMEM   (16384 + 2 * 16384) // Q + 2 KV stages

// ---------------- scratch -----------------------------------------------
__device__ float g_y  [MROWS * DM];

__device__ __half t_xr [MROWS * DM];
__device__ __half t_xn [MROWS * DM];
__device__ __half t_q  [MROWS * DM];
__device__ __half t_k  [MROWS * DM];
__device__ __half t_v  [MROWS * DM];
__device__ __half t_ctx[MROWS * DM];
__device__ __half t_yn [MROWS * DM];
__device__ __half t_h  [MROWS * FF];
__device__ __half t_wqkv[3072 * DM];    // wqk (rows 0..2047) + wv (2048..3071), tile-contiguous
__device__ __half t_wo [DM * DM];
__device__ __half t_w1 [FF * DM];
__device__ __half t_w2 [DM * FF];

// ---------------- helpers -----------------------------------------------
__device__ __forceinline__ uint32_t sw128(uint32_t o) { return o ^ ((o >> 3) & 0x70); }

__device__ __forceinline__ float fexp(float x)
{
    x = fminf(fmaxf(x, -87.f), 87.f);
    float y = x * 1.4426950408889634f;
    float r = rintf(y);
    float f = y - r;
    float p = 1.33336498e-3f;
    p = fmaf(p, f, 9.61793571e-3f);
    p = fmaf(p, f, 5.55043442e-2f);
    p = fmaf(p, f, 2.40226507e-1f);
    p = fmaf(p, f, 6.93147182e-1f);
    p = fmaf(p, f, 1.0f);
    return p * __int_as_float(((int)r + 127) << 23);
}

__device__ __forceinline__ uint32_t smem_u32(const void* p)
{
    uint32_t a;
    asm("{ .reg .u64 t; cvta.to.shared.u64 t, %1; cvt.u32.u64 %0, t; }" : "=r"(a) : "l"(p));
    return a;
}

__device__ __forceinline__ void cp16(uint32_t s, const void* g)
{
    asm volatile("cp.async.cg.shared.global [%0], [%1], 16;" :: "r"(s), "l"(g));
}

__device__ __forceinline__ void ldsm4(uint32_t* r, uint32_t addr)
{
    asm volatile("ldmatrix.sync.aligned.m8n8.x4.shared.b16 {%0,%1,%2,%3}, [%4];"
                 : "=r"(r[0]), "=r"(r[1]), "=r"(r[2]), "=r"(r[3]) : "r"(addr));
}

__device__ __forceinline__ void ldsm4t(uint32_t* r, uint32_t addr)
{
    asm volatile("ldmatrix.sync.aligned.m8n8.x4.trans.shared.b16 {%0,%1,%2,%3}, [%4];"
                 : "=r"(r[0]), "=r"(r[1]), "=r"(r[2]), "=r"(r[3]) : "r"(addr));
}

__device__ __forceinline__ void mma_f16(float* d, const uint32_t* a, const uint32_t* b)
{
    asm volatile(
        "mma.sync.aligned.m16n8k16.row.col.f32.f16.f16.f32 "
        "{%0,%1,%2,%3}, {%4,%5,%6,%7}, {%8,%9}, {%0,%1,%2,%3};"
        : "+f"(d[0]), "+f"(d[1]), "+f"(d[2]), "+f"(d[3])
        : "r"(a[0]), "r"(a[1]), "r"(a[2]), "r"(a[3]), "r"(b[0]), "r"(b[1]));
}

__device__ __forceinline__ uint32_t pack_h2(float x, float y)
{
    __half2 t = __floats2half2_rn(x, y);
    return *(uint32_t*)&t;
}

// ---------------- RMSNorm (+ optional RoPE) -> tiled fp16 ----------------
__global__ void __launch_bounds__(256) rms_rope_kernel(
    const float* __restrict__ x, const float* __restrict__ scale,
    __half* __restrict__ n_out, __half* __restrict__ r_out)
{
    const int row = blockIdx.x;
    const int tid = threadIdx.x;
    __shared__ float red[8];
    __shared__ float th[32];

    if (tid < 32)
        th[tid] = (float)exp(-((double)(2 * tid) / 64.0) * 9.210340371976184);

    float4 v = *(const float4*)(x + (size_t)row * DM + tid * 4);
    float ss = v.x * v.x + v.y * v.y + v.z * v.z + v.w * v.w;
    #pragma unroll
    for (int o = 16; o > 0; o >>= 1) ss += __shfl_xor_sync(0xffffffffu, ss, o);
    if ((tid & 31) == 0) red[tid >> 5] = ss;
    __syncthreads();
    float tot = 0.f;
    #pragma unroll
    for (int i = 0; i < 8; i++) tot += red[i];
    const float r = rsqrtf(tot * (1.0f / (float)DM) + 1e-6f);

    float4 sc = *(const float4*)(scale + tid * 4);
    float4 n;
    n.x = v.x * r * sc.x;
    n.y = v.y * r * sc.y;
    n.z = v.z * r * sc.z;
    n.w = v.w * r * sc.w;

    const int mt = row >> 7, rr = row & 127;
    const int c0 = tid * 4;
    const int kc = c0 >> 6, kk = c0 & 63;
    const size_t base = ((size_t)mt * (DM / 64) + kc) * TILE_ELEMS;
    const uint32_t off = sw128(rr * 128 + kk * 2) >> 1;
    {
        uint2 pk;
        pk.x = pack_h2(n.x, n.y);
        pk.y = pack_h2(n.z, n.w);
        *(uint2*)(n_out + base + off) = pk;
    }

    if (r_out != nullptr) {
        const int t = row & (SEQ - 1);
        const int c = c0 & (HD - 1);
        const int p = c >> 1;
        float a0 = (float)t * th[p];
        float a1 = (float)t * th[p + 1];
        float s0, co0, s1, co1;
        sincosf(a0, &s0, &co0);
        sincosf(a1, &s1, &co1);
        uint2 pk;
        pk.x = pack_h2(n.x * co0 - n.y * s0, n.y * co0 + n.x * s0);
        pk.y = pack_h2(n.z * co1 - n.w * s1, n.w * co1 + n.z * s1);
        *(uint2*)(r_out + base + off) = pk;
    }
}

// ---------------- fp32 [N,K] -> tiled fp16 (vectorized) ------------------
__global__ void __launch_bounds__(256) conv_tiled_kernel(
    const float* __restrict__ in, int K, __half* __restrict__ out)
{
    const int kc = blockIdx.x;
    const int rt = blockIdx.y;
    const int NCk = gridDim.x;
    const size_t base = ((size_t)rt * NCk + kc) * (size_t)TILE_ELEMS;
    #pragma unroll
    for (int idx = threadIdx.x; idx < 1024; idx += 256) {
        const int r = idx >> 3, k = (idx & 7) * 8;
        const float* gp = in + (size_t)(rt * 128 + r) * K + kc * 64 + k;
        const float4 a = *(const float4*)gp;
        const float4 b = *(const float4*)(gp + 4);
        uint4 pk;
        pk.x = pack_h2(a.x, a.y);
        pk.y = pack_h2(a.z, a.w);
        pk.z = pack_h2(b.x, b.y);
        pk.w = pack_h2(b.z, b.w);
        const uint32_t off = sw128(r * 128 + k * 2) >> 1;
        *(uint4*)(out + base + off) = pk;
    }
}

// ---------------- mma.sync fp16 GEMM (3-stage pipeline, 2 CTA/SM) --------
// OUTT: 0 = fp32 row-major C (optional residual), 1 = fp16 tiled O,
//       2 = fp16 tiled split: n<1024 -> O, n>=1024 -> O2
template <int ACT, int RES, int OUTT>
__global__ void __launch_bounds__(256, 2) gemm_mma(
    const __half* __restrict__ A, const __half* __restrict__ B,
    const float* __restrict__ bias, const float* __restrict__ resid,
    float* __restrict__ C, __half* __restrict__ O, __half* __restrict__ O2,
    int N, int K)
{
    extern __shared__ char smem[];
    const uint32_t sbase = (smem_u32(smem) + 127) & ~127u;

    const int tid = threadIdx.x;
    const int lane = tid & 31, wid = tid >> 5;
    const int wm = wid >> 1, wn = wid & 1;
    const int NC = K >> 6;
    const int mt = blockIdx.y, nt = blockIdx.x;

    const uint32_t xr = (uint32_t)((lane & 7) << 4);
    uint32_t aRow[2];
    #pragma unroll
    for (int mi = 0; mi < 2; mi++)
        aRow[mi] = (uint32_t)((wm * 32 + mi * 16 + (lane & 15)) * 128);
    const uint32_t kA = (uint32_t)((lane >> 4) * 16);

    const int nb = wn * 64 + ((lane >> 4) << 3) + (lane & 7);
    uint32_t bRow[4];
    #pragma unroll
    for (int np = 0; np < 4; np++)
        bRow[np] = (uint32_t)((nb + np * 16) * 128);
    const uint32_t kB = (uint32_t)(((lane >> 3) & 1) * 16);

    float acc[2][8][4];
    #pragma unroll
    for (int mi = 0; mi < 2; mi++)
        #pragma unroll
        for (int nj = 0; nj < 8; nj++)
            #pragma unroll
            for (int q = 0; q < 4; q++) acc[mi][nj][q] = 0.f;

    auto load_chunk = [&](int i) {
        const uint32_t st = sbase + (uint32_t)(i % NSTAGE) * STAGE_BYTES;
        const char* ga = (const char*)(A + ((size_t)mt * NC + i) * TILE_ELEMS);
        const char* gb = (const char*)(B + ((size_t)nt * NC + i) * TILE_ELEMS);
        #pragma unroll 4
        for (int j = tid; j < 1024; j += 256) {
            cp16(st + j * 16,         ga + j * 16);
            cp16(st + 16384 + j * 16, gb + j * 16);
        }
        asm volatile("cp.async.commit_group;" ::: "memory");
    };

    load_chunk(0);
    if (NC > 1) load_chunk(1);
    for (int i = 0; i < NC; i++) {
        // prefetch i+2 first (buffer (i+2)%3 was freed by the sync at end of i-1)
        if (i + 2 < NC) {
            load_chunk(i + 2);
            asm volatile("cp.async.wait_group 2;" ::: "memory");
        } else if (i + 1 < NC) {
            asm volatile("cp.async.wait_group 1;" ::: "memory");
        } else {
            asm volatile("cp.async.wait_group 0;" ::: "memory");
        }
        __syncthreads();

        const uint32_t st = sbase + (uint32_t)(i % NSTAGE) * STAGE_BYTES;
        const uint32_t sA = st, sB = st + 16384;

        #pragma unroll
        for (int ks = 0; ks < 4; ks++) {
            const uint32_t ka = (uint32_t)(ks * 32) + kA;
            const uint32_t kb = (uint32_t)(ks * 32) + kB;
            uint32_t a[2][4], b[4][4];
            #pragma unroll
            for (int mi = 0; mi < 2; mi++)
                ldsm4(a[mi], sA + aRow[mi] + (ka ^ xr));
            #pragma unroll
            for (int np = 0; np < 4; np++)
                ldsm4(b[np], sB + bRow[np] + (kb ^ xr));
            #pragma unroll
            for (int mi = 0; mi < 2; mi++)
                #pragma unroll
                for (int nj = 0; nj < 8; nj++)
                    mma_f16(acc[mi][nj], a[mi], &b[nj >> 1][(nj & 1) * 2]);
        }
        __syncthreads();
    }

    const int m_base = mt * 128 + wm * 32 + (lane >> 2);
    const int n_base = nt * 128 + wn * 64 + (lane & 3) * 2;
    #pragma unroll
    for (int mi = 0; mi < 2; mi++) {
        #pragma unroll
        for (int nj = 0; nj < 8; nj++) {
            const int n = n_base + nj * 8;
            const float b0 = bias[n], b1 = bias[n + 1];
            float v00 = acc[mi][nj][0] + b0, v01 = acc[mi][nj][1] + b1;
            float v10 = acc[mi][nj][2] + b0, v11 = acc[mi][nj][3] + b1;
            if (ACT == 1) {
                v00 = v00 / (1.0f + fexp(-v00));
                v01 = v01 / (1.0f + fexp(-v01));
                v10 = v10 / (1.0f + fexp(-v10));
                v11 = v11 / (1.0f + fexp(-v11));
            }
            const int m0 = m_base + mi * 16, m1 = m0 + 8;
            if (OUTT >= 1) {
                int kc = n >> 6;
                __half* Od = O;
                int ntiles = N >> 6;
                if (OUTT == 2) {
                    ntiles = 16;
                    if (kc >= 16) { Od = O2; kc -= 16; }
                }
                const int kk = n & 63;
                const size_t tb = ((size_t)mt * ntiles + kc) * TILE_ELEMS;
                const uint32_t o0 = sw128((m0 & 127) * 128 + kk * 2) >> 1;
                const uint32_t o1 = sw128((m1 & 127) * 128 + kk * 2) >> 1;
                *(uint32_t*)(Od + tb + o0) = pack_h2(v00, v01);
                *(uint32_t*)(Od + tb + o1) = pack_h2(v10, v11);
            } else {
                const size_t o0 = (size_t)m0 * N + n;
                const size_t o1 = (size_t)m1 * N + n;
                if (RES == 1) {
                    float2 r0 = *(const float2*)(resid + o0);
                    float2 r1 = *(const float2*)(resid + o1);
                    v00 += r0.x; v01 += r0.y; v10 += r1.x; v11 += r1.y;
                }
                *(float2*)(C + o0) = make_float2(v00, v01);
                *(float2*)(C + o1) = make_float2(v10, v11);
            }
        }
    }
}

// ---------------- tensor-core causal flash attention ---------------------
// grid (16 qtiles, 16 heads, 2 batch), 256 thr = 8 warps x 16 q-rows
__global__ void __launch_bounds__(256, 2) flash_mma_kernel(
    const __half* __restrict__ Q, const __half* __restrict__ K,
    const __half* __restrict__ V, __half* __restrict__ Cc)
{
    extern __shared__ char smem[];
    const uint32_t sbase = smem_u32(smem);

    const int tid = threadIdx.x, lane = tid & 31, wq = tid >> 5;
    const int qt = 15 - blockIdx.x;           // big tiles first
    const int h = blockIdx.y, b = blockIdx.z;
    const int mtq = b * 16 + qt;
    const int KT = 2 * qt + 2;

    const uint32_t sQ = sbase;

    // Q tile async load
    {
        const char* gQ = (const char*)(Q + ((size_t)mtq * 16 + h) * TILE_ELEMS);
        for (int j = tid; j < 1024; j += 256)
            cp16(sQ + j * 16, gQ + j * 16);
        asm volatile("cp.async.commit_group;" ::: "memory");
    }

    auto load_kv = [&](int kt) {
        const uint32_t st = sbase + 16384 + (uint32_t)(kt & 1) * 16384;
        const int mtk = b * 16 + (kt >> 1);
        const size_t toff = ((size_t)mtk * 16 + h) * TILE_ELEMS + (size_t)(kt & 1) * 4096;
        const char* gk = (const char*)(K + toff);
        const char* gv = (const char*)(V + toff);
        for (int j = tid; j < 512; j += 256) {
            cp16(st + j * 16,        gk + j * 16);
            cp16(st + 8192 + j * 16, gv + j * 16);
        }
        asm volatile("cp.async.commit_group;" ::: "memory");
    };
    load_kv(0);
    asm volatile("cp.async.wait_group 0;" ::: "memory");
    __syncthreads();

    // Q A-fragments
    const uint32_t xr = (uint32_t)((lane & 7) << 4);
    const uint32_t aRow = (uint32_t)((wq * 16 + (lane & 15)) * 128);
    const uint32_t kA = (uint32_t)((lane >> 4) * 16);
    uint32_t qf[4][4];
    #pragma unroll
    for (int ks = 0; ks < 4; ks++)
        ldsm4(qf[ks], sQ + aRow + (((uint32_t)(ks * 32) + kA) ^ xr));

    float o[8][4];
    #pragma unroll
    for (int nj = 0; nj < 8; nj++)
        #pragma unroll
        for (int q = 0; q < 4; q++) o[nj][q] = 0.f;
    float m0 = -1e30f, m1 = -1e30f, l0 = 0.f, l1 = 0.f;

    const uint32_t nbK = (uint32_t)(((lane >> 4) << 3) + (lane & 7));
    const uint32_t kB = (uint32_t)(((lane >> 3) & 1) * 16);
    const int vmi = lane >> 3, vri = lane & 7;

    const int row_lo = qt * 128 + wq * 16;

    for (int kt = 0; kt < KT; kt++) {
        if (kt + 1 < KT) {
            load_kv(kt + 1);
            asm volatile("cp.async.wait_group 1;" ::: "memory");
        } else {
            asm volatile("cp.async.wait_group 0;" ::: "memory");
        }
        __syncthreads();

        if (kt * 64 <= row_lo + 15) {
            const uint32_t st = sbase + 16384 + (uint32_t)(kt & 1) * 16384;
            const uint32_t sK = st, sV = st + 8192;

            float S[8][4];
            #pragma unroll
            for (int nj = 0; nj < 8; nj++)
                #pragma unroll
                for (int q = 0; q < 4; q++) S[nj][q] = 0.f;

            #pragma unroll
            for (int ks = 0; ks < 4; ks++) {
                const uint32_t kb = (uint32_t)(ks * 32) + kB;
                uint32_t bk[4][4];
                #pragma unroll
                for (int np = 0; np < 4; np++)
                    ldsm4(bk[np], sK + (nbK + np * 16) * 128 + (kb ^ xr));
                #pragma unroll
                for (int nj = 0; nj < 8; nj++)
                    mma_f16(S[nj], qf[ks], &bk[nj >> 1][(nj & 1) * 2]);
            }

            const int r0 = row_lo + (lane >> 2);
            const bool need_mask = (kt * 64 + 63) > row_lo;
            #pragma unroll
            for (int nj = 0; nj < 8; nj++)
                #pragma unroll
                for (int q = 0; q < 4; q++) S[nj][q] *= 0.125f;
            if (need_mask) {
                #pragma unroll
                for (int nj = 0; nj < 8; nj++)
                    #pragma unroll
                    for (int q = 0; q < 4; q++) {
                        const int kg = kt * 64 + nj * 8 + (lane & 3) * 2 + (q & 1);
                        const int qg = r0 + ((q >= 2) ? 8 : 0);
                        if (kg > qg) S[nj][q] = -1e30f;
                    }
            }

            float t0 = -1e30f, t1 = -1e30f;
            #pragma unroll
            for (int nj = 0; nj < 8; nj++) {
                t0 = fmaxf(t0, fmaxf(S[nj][0], S[nj][1]));
                t1 = fmaxf(t1, fmaxf(S[nj][2], S[nj][3]));
            }
            t0 = fmaxf(t0, __shfl_xor_sync(0xffffffffu, t0, 1));
            t0 = fmaxf(t0, __shfl_xor_sync(0xffffffffu, t0, 2));
            t1 = fmaxf(t1, __shfl_xor_sync(0xffffffffu, t1, 1));
            t1 = fmaxf(t1, __shfl_xor_sync(0xffffffffu, t1, 2));
            const float mn0 = fmaxf(m0, t0), mn1 = fmaxf(m1, t1);
            const float c0 = fexp(m0 - mn0), c1 = fexp(m1 - mn1);
            m0 = mn0; m1 = mn1;
            l0 *= c0; l1 *= c1;
            #pragma unroll
            for (int nj = 0; nj < 8; nj++) {
                o[nj][0] *= c0; o[nj][1] *= c0;
                o[nj][2] *= c1; o[nj][3] *= c1;
            }
            float ls0 = 0.f, ls1 = 0.f;
            #pragma unroll
            for (int nj = 0; nj < 8; nj++) {
                S[nj][0] = fexp(S[nj][0] - mn0); ls0 += S[nj][0];
                S[nj][1] = fexp(S[nj][1] - mn0); ls0 += S[nj][1];
                S[nj][2] = fexp(S[nj][2] - mn1); ls1 += S[nj][2];
                S[nj][3] = fexp(S[nj][3] - mn1); ls1 += S[nj][3];
            }
            l0 += ls0; l1 += ls1;

            // P @ V (V via ldmatrix.trans)
            #pragma unroll
            for (int kk = 0; kk < 4; kk++) {
                uint32_t ap[4];
                ap[0] = pack_h2(S[2*kk][0],   S[2*kk][1]);
                ap[1] = pack_h2(S[2*kk][2],   S[2*kk][3]);
                ap[2] = pack_h2(S[2*kk+1][0], S[2*kk+1][1]);
                ap[3] = pack_h2(S[2*kk+1][2], S[2*kk+1][3]);
                uint32_t vf[4][4];
                const uint32_t vrow = (uint32_t)(kk * 16 + (vmi & 1) * 8 + vri);
                #pragma unroll
                for (int g = 0; g < 4; g++) {
                    const uint32_t off = sw128(vrow * 128 + (uint32_t)(g * 16 + (vmi >> 1) * 8) * 2);
                    ldsm4t(vf[g], sV + off);
                }
                #pragma unroll
                for (int nj = 0; nj < 8; nj++)
                    mma_f16(o[nj], ap, &vf[nj >> 1][(nj & 1) * 2]);
            }
        }
        __syncthreads();
    }

    l0 += __shfl_xor_sync(0xffffffffu, l0, 1);
    l0 += __shfl_xor_sync(0xffffffffu, l0, 2);
    l1 += __shfl_xor_sync(0xffffffffu, l1, 1);
    l1 += __shfl_xor_sync(0xffffffffu, l1, 2);
    const float inv0 = 1.0f / l0, inv1 = 1.0f / l1;

    const size_t tb = ((size_t)mtq * 16 + h) * TILE_ELEMS;
    const int rl0 = wq * 16 + (lane >> 2), rl1 = rl0 + 8;
    #pragma unroll
    for (int nj = 0; nj < 8; nj++) {
        const int col = nj * 8 + (lane & 3) * 2;
        const uint32_t o0 = sw128(rl0 * 128 + col * 2) >> 1;
        const uint32_t o1 = sw128(rl1 * 128 + col * 2) >> 1;
        *(uint32_t*)(Cc + tb + o0) = pack_h2(o[nj][0] * inv0, o[nj][1] * inv0);
        *(uint32_t*)(Cc + tb + o1) = pack_h2(o[nj][2] * inv1, o[nj][3] * inv1);
    }
}

// ---------------- launch -------------------------------------------------
#define SYMADDR(p, s) cudaGetSymbolAddress((void**)&(p), s)

extern "C" void kernel_launch(void* const* d_in, const int* in_sizes, int n_in,
                              void* d_out, int out_size)
{
    const float* x         = (const float*)d_in[0];
    const float* rms_scale = (const float*)d_in[1];
    const float* in_proj_w = (const float*)d_in[2];
    const float* in_proj_b = (const float*)d_in[3];
    const float* out_proj_w= (const float*)d_in[4];
    const float* out_proj_b= (const float*)d_in[5];
    const float* w1        = (const float*)d_in[6];
    const float* b1        = (const float*)d_in[7];
    const float* w2        = (const float*)d_in[8];
    const float* b2        = (const float*)d_in[9];
    float* out = (float*)d_out;

    float *p_y;
    __half *xr, *xn, *q, *k, *v, *ctx, *yn, *hh;
    __half *wqkv, *wo, *w1h, *w2h;
    SYMADDR(p_y, g_y);
    SYMADDR(xr, t_xr);   SYMADDR(xn, t_xn);
    SYMADDR(q, t_q);     SYMADDR(k, t_k);    SYMADDR(v, t_v);
    SYMADDR(ctx, t_ctx); SYMADDR(yn, t_yn);  SYMADDR(hh, t_h);
    SYMADDR(wqkv, t_wqkv); SYMADDR(wo, t_wo);
    SYMADDR(w1h, t_w1);  SYMADDR(w2h, t_w2);
    __half* wv = wqkv + (size_t)2048 * DM;

    cudaFuncSetAttribute(gemm_mma<0,0,0>, cudaFuncAttributeMaxDynamicSharedMemorySize, GEMM_SMEM);
    cudaFuncSetAttribute(gemm_mma<0,0,1>, cudaFuncAttributeMaxDynamicSharedMemorySize, GEMM_SMEM);
    cudaFuncSetAttribute(gemm_mma<0,0,2>, cudaFuncAttributeMaxDynamicSharedMemorySize, GEMM_SMEM);
    cudaFuncSetAttribute(gemm_mma<1,0,1>, cudaFuncAttributeMaxDynamicSharedMemorySize, GEMM_SMEM);
    cudaFuncSetAttribute(gemm_mma<0,1,0>, cudaFuncAttributeMaxDynamicSharedMemorySize, GEMM_SMEM);
    cudaFuncSetAttribute(flash_mma_kernel, cudaFuncAttributeMaxDynamicSharedMemorySize, ATTN_SMEM);

    // weight conversions -> tiled fp16
    conv_tiled_kernel<<<dim3(16, 24), 256>>>(in_proj_w,  DM, wqkv);   // Wq|Wk|Wv
    conv_tiled_kernel<<<dim3(16, 8),  256>>>(out_proj_w, DM, wo);
    conv_tiled_kernel<<<dim3(16, 32), 256>>>(w1,         DM, w1h);
    conv_tiled_kernel<<<dim3(64, 8),  256>>>(w2,         FF, w2h);

    // 1) xn = rmsnorm(x); xr = rope(xn)
    rms_rope_kernel<<<MROWS, 256>>>(x, rms_scale, xn, xr);

    // 2) [q|k] = xr @ [Wq;Wk]^T + b (N=2048, split outputs), v = xn @ Wv^T
    gemm_mma<0,0,2><<<dim3(16, 32), 256, GEMM_SMEM>>>(
        xr, wqkv, in_proj_b, nullptr, nullptr, q, k, 2 * DM, DM);
    gemm_mma<0,0,1><<<dim3(8, 32), 256, GEMM_SMEM>>>(
        xn, wv, in_proj_b + 2 * DM, nullptr, nullptr, v, nullptr, DM, DM);

    // 3) tensor-core causal attention -> ctx tiles
    flash_mma_kernel<<<dim3(16, NH, BATCH), 256, ATTN_SMEM>>>(q, k, v, ctx);

    // 4) y = ctx @ Wo^T + b
    gemm_mma<0,0,0><<<dim3(8, 32), 256, GEMM_SMEM>>>(
        ctx, wo, out_proj_b, nullptr, p_y, nullptr, nullptr, DM, DM);

    // 5) yn = rmsnorm(y)
    rms_rope_kernel<<<MROWS, 256>>>(p_y, rms_scale, yn, nullptr);

    // 6) h = silu(yn @ w1^T + b1) -> tiled fp16
    gemm_mma<1,0,1><<<dim3(32, 32), 256, GEMM_SMEM>>>(
        yn, w1h, b1, nullptr, nullptr, hh, nullptr, FF, DM);

    // 7) out = y + (h @ w2^T + b2)
    gemm_mma<0,1,0><<<dim3(8, 32), 256, GEMM_SMEM>>>(
        hh, w2h, b2, p_y, out, nullptr, nullptr, DM, FF);
}

// round 8
// speedup vs baseline: 7.7030x; 1.0365x over previous
#include <cuda_runtime.h>
#include <cuda_fp16.h>
#include <cstdint>
#include <math.h>

// Problem constants
#define BATCH 2
#define SEQ   2048
#define DM    1024
#define NH    16
#define HD    64
#define FF    4096
#define MROWS (BATCH * SEQ)   // 4096

#define TILE_ELEMS 8192                 // 128 rows x 64 fp16 (SW128)
#define TILE_BYTES 16384
#define STAGE_BYTES 32768               // A tile + B tile
#define NSTAGE 3
#define GEMM_SMEM   (NSTAGE * STAGE_BYTES + 256)
#define ATTN_SMEM   (16384 + 2 * 16384) // Q + 2 KV stages

// ---------------- scratch -----------------------------------------------
__device__ float g_y  [MROWS * DM];

__device__ __half t_xr [MROWS * DM];
__device__ __half t_xn [MROWS * DM];
__device__ __half t_q  [MROWS * DM];
__device__ __half t_k  [MROWS * DM];
__device__ __half t_v  [MROWS * DM];
__device__ __half t_ctx[MROWS * DM];
__device__ __half t_yn [MROWS * DM];
__device__ __half t_h  [MROWS * FF];
__device__ __half t_wqkv[3072 * DM];    // Wq|Wk|Wv tile-contiguous
__device__ __half t_wo [DM * DM];
__device__ __half t_w1 [FF * DM];
__device__ __half t_w2 [DM * FF];

// ---------------- helpers -----------------------------------------------
__device__ __forceinline__ uint32_t sw128(uint32_t o) { return o ^ ((o >> 3) & 0x70); }

__device__ __forceinline__ float fexp(float x)
{
    x = fminf(fmaxf(x, -87.f), 87.f);
    float y = x * 1.4426950408889634f;
    float r = rintf(y);
    float f = y - r;
    float p = 1.33336498e-3f;
    p = fmaf(p, f, 9.61793571e-3f);
    p = fmaf(p, f, 5.55043442e-2f);
    p = fmaf(p, f, 2.40226507e-1f);
    p = fmaf(p, f, 6.93147182e-1f);
    p = fmaf(p, f, 1.0f);
    return p * __int_as_float(((int)r + 127) << 23);
}

__device__ __forceinline__ uint32_t smem_u32(const void* p)
{
    uint32_t a;
    asm("{ .reg .u64 t; cvta.to.shared.u64 t, %1; cvt.u32.u64 %0, t; }" : "=r"(a) : "l"(p));
    return a;
}

__device__ __forceinline__ void cp16(uint32_t s, const void* g)
{
    asm volatile("cp.async.cg.shared.global [%0], [%1], 16;" :: "r"(s), "l"(g));
}

__device__ __forceinline__ void ldsm4(uint32_t* r, uint32_t addr)
{
    asm volatile("ldmatrix.sync.aligned.m8n8.x4.shared.b16 {%0,%1,%2,%3}, [%4];"
                 : "=r"(r[0]), "=r"(r[1]), "=r"(r[2]), "=r"(r[3]) : "r"(addr));
}

__device__ __forceinline__ void ldsm4t(uint32_t* r, uint32_t addr)
{
    asm volatile("ldmatrix.sync.aligned.m8n8.x4.trans.shared.b16 {%0,%1,%2,%3}, [%4];"
                 : "=r"(r[0]), "=r"(r[1]), "=r"(r[2]), "=r"(r[3]) : "r"(addr));
}

__device__ __forceinline__ void mma_f16(float* d, const uint32_t* a, const uint32_t* b)
{
    asm volatile(
        "mma.sync.aligned.m16n8k16.row.col.f32.f16.f16.f32 "
        "{%0,%1,%2,%3}, {%4,%5,%6,%7}, {%8,%9}, {%0,%1,%2,%3};"
        : "+f"(d[0]), "+f"(d[1]), "+f"(d[2]), "+f"(d[3])
        : "r"(a[0]), "r"(a[1]), "r"(a[2]), "r"(a[3]), "r"(b[0]), "r"(b[1]));
}

__device__ __forceinline__ uint32_t pack_h2(float x, float y)
{
    __half2 t = __floats2half2_rn(x, y);
    return *(uint32_t*)&t;
}

// ---------------- RMSNorm (+ optional RoPE) -> tiled fp16 ----------------
__global__ void __launch_bounds__(256) rms_rope_kernel(
    const float* __restrict__ x, const float* __restrict__ scale,
    __half* __restrict__ n_out, __half* __restrict__ r_out)
{
    const int row = blockIdx.x;
    const int tid = threadIdx.x;
    __shared__ float red[8];
    __shared__ float th[32];

    if (r_out != nullptr && tid < 32)
        th[tid] = exp2f((float)tid * (-13.287712379549449f / 32.0f));

    float4 v = *(const float4*)(x + (size_t)row * DM + tid * 4);
    float ss = v.x * v.x + v.y * v.y + v.z * v.z + v.w * v.w;
    #pragma unroll
    for (int o = 16; o > 0; o >>= 1) ss += __shfl_xor_sync(0xffffffffu, ss, o);
    if ((tid & 31) == 0) red[tid >> 5] = ss;
    __syncthreads();
    float tot = 0.f;
    #pragma unroll
    for (int i = 0; i < 8; i++) tot += red[i];
    const float r = rsqrtf(tot * (1.0f / (float)DM) + 1e-6f);

    float4 sc = *(const float4*)(scale + tid * 4);
    float4 n;
    n.x = v.x * r * sc.x;
    n.y = v.y * r * sc.y;
    n.z = v.z * r * sc.z;
    n.w = v.w * r * sc.w;

    const int mt = row >> 7, rr = row & 127;
    const int c0 = tid * 4;
    const int kc = c0 >> 6, kk = c0 & 63;
    const size_t base = ((size_t)mt * (DM / 64) + kc) * TILE_ELEMS;
    const uint32_t off = sw128(rr * 128 + kk * 2) >> 1;
    {
        uint2 pk;
        pk.x = pack_h2(n.x, n.y);
        pk.y = pack_h2(n.z, n.w);
        *(uint2*)(n_out + base + off) = pk;
    }

    if (r_out != nullptr) {
        const int t = row & (SEQ - 1);
        const int c = c0 & (HD - 1);
        const int p = c >> 1;
        float a0 = (float)t * th[p];
        float a1 = (float)t * th[p + 1];
        float s0, co0, s1, co1;
        sincosf(a0, &s0, &co0);
        sincosf(a1, &s1, &co1);
        uint2 pk;
        pk.x = pack_h2(n.x * co0 - n.y * s0, n.y * co0 + n.x * s0);
        pk.y = pack_h2(n.z * co1 - n.w * s1, n.w * co1 + n.z * s1);
        *(uint2*)(r_out + base + off) = pk;
    }
}

// ---------------- fp32 [N,K] -> tiled fp16 (vectorized) ------------------
__global__ void __launch_bounds__(256) conv_tiled_kernel(
    const float* __restrict__ in, int K, __half* __restrict__ out)
{
    const int kc = blockIdx.x;
    const int rt = blockIdx.y;
    const int NCk = gridDim.x;
    const size_t base = ((size_t)rt * NCk + kc) * (size_t)TILE_ELEMS;
    #pragma unroll
    for (int idx = threadIdx.x; idx < 1024; idx += 256) {
        const int r = idx >> 3, k = (idx & 7) * 8;
        const float* gp = in + (size_t)(rt * 128 + r) * K + kc * 64 + k;
        const float4 a = *(const float4*)gp;
        const float4 b = *(const float4*)(gp + 4);
        uint4 pk;
        pk.x = pack_h2(a.x, a.y);
        pk.y = pack_h2(a.z, a.w);
        pk.z = pack_h2(b.x, b.y);
        pk.w = pack_h2(b.z, b.w);
        const uint32_t off = sw128(r * 128 + k * 2) >> 1;
        *(uint4*)(out + base + off) = pk;
    }
}

// ---------------- mma.sync fp16 GEMM (3-stage pipeline, 2 CTA/SM) --------
// OUTT: 0 = fp32 row-major C (optional residual), 1 = fp16 tiled O,
//       2 = fp16 tiled split: n<1024 -> O, n>=1024 -> O2
template <int ACT, int RES, int OUTT>
__global__ void __launch_bounds__(256, 2) gemm_mma(
    const __half* __restrict__ A, const __half* __restrict__ B,
    const float* __restrict__ bias, const float* __restrict__ resid,
    float* __restrict__ C, __half* __restrict__ O, __half* __restrict__ O2,
    int N, int K)
{
    extern __shared__ char smem[];
    const uint32_t sbase = (smem_u32(smem) + 127) & ~127u;

    const int tid = threadIdx.x;
    const int lane = tid & 31, wid = tid >> 5;
    const int wm = wid >> 1, wn = wid & 1;
    const int NC = K >> 6;
    const int mt = blockIdx.y, nt = blockIdx.x;

    const uint32_t xr = (uint32_t)((lane & 7) << 4);
    uint32_t aRow[2];
    #pragma unroll
    for (int mi = 0; mi < 2; mi++)
        aRow[mi] = (uint32_t)((wm * 32 + mi * 16 + (lane & 15)) * 128);
    const uint32_t kA = (uint32_t)((lane >> 4) * 16);

    const int nb = wn * 64 + ((lane >> 4) << 3) + (lane & 7);
    uint32_t bRow[4];
    #pragma unroll
    for (int np = 0; np < 4; np++)
        bRow[np] = (uint32_t)((nb + np * 16) * 128);
    const uint32_t kB = (uint32_t)(((lane >> 3) & 1) * 16);

    float acc[2][8][4];
    #pragma unroll
    for (int mi = 0; mi < 2; mi++)
        #pragma unroll
        for (int nj = 0; nj < 8; nj++)
            #pragma unroll
            for (int q = 0; q < 4; q++) acc[mi][nj][q] = 0.f;

    auto load_chunk = [&](int i) {
        const uint32_t st = sbase + (uint32_t)(i % NSTAGE) * STAGE_BYTES;
        const char* ga = (const char*)(A + ((size_t)mt * NC + i) * TILE_ELEMS);
        const char* gb = (const char*)(B + ((size_t)nt * NC + i) * TILE_ELEMS);
        #pragma unroll 4
        for (int j = tid; j < 1024; j += 256) {
            cp16(st + j * 16,         ga + j * 16);
            cp16(st + 16384 + j * 16, gb + j * 16);
        }
        asm volatile("cp.async.commit_group;" ::: "memory");
    };

    load_chunk(0);
    if (NC > 1) load_chunk(1);
    for (int i = 0; i < NC; i++) {
        if (i + 2 < NC) {
            load_chunk(i + 2);
            asm volatile("cp.async.wait_group 2;" ::: "memory");
        } else if (i + 1 < NC) {
            asm volatile("cp.async.wait_group 1;" ::: "memory");
        } else {
            asm volatile("cp.async.wait_group 0;" ::: "memory");
        }
        __syncthreads();

        const uint32_t st = sbase + (uint32_t)(i % NSTAGE) * STAGE_BYTES;
        const uint32_t sA = st, sB = st + 16384;

        #pragma unroll
        for (int ks = 0; ks < 4; ks++) {
            const uint32_t ka = (uint32_t)(ks * 32) + kA;
            const uint32_t kb = (uint32_t)(ks * 32) + kB;
            uint32_t a[2][4], b[4][4];
            #pragma unroll
            for (int mi = 0; mi < 2; mi++)
                ldsm4(a[mi], sA + aRow[mi] + (ka ^ xr));
            #pragma unroll
            for (int np = 0; np < 4; np++)
                ldsm4(b[np], sB + bRow[np] + (kb ^ xr));
            #pragma unroll
            for (int mi = 0; mi < 2; mi++)
                #pragma unroll
                for (int nj = 0; nj < 8; nj++)
                    mma_f16(acc[mi][nj], a[mi], &b[nj >> 1][(nj & 1) * 2]);
        }
        __syncthreads();
    }

    const int m_base = mt * 128 + wm * 32 + (lane >> 2);
    const int n_base = nt * 128 + wn * 64 + (lane & 3) * 2;
    #pragma unroll
    for (int mi = 0; mi < 2; mi++) {
        #pragma unroll
        for (int nj = 0; nj < 8; nj++) {
            const int n = n_base + nj * 8;
            const float b0 = bias[n], b1 = bias[n + 1];
            float v00 = acc[mi][nj][0] + b0, v01 = acc[mi][nj][1] + b1;
            float v10 = acc[mi][nj][2] + b0, v11 = acc[mi][nj][3] + b1;
            if (ACT == 1) {
                v00 = v00 / (1.0f + fexp(-v00));
                v01 = v01 / (1.0f + fexp(-v01));
                v10 = v10 / (1.0f + fexp(-v10));
                v11 = v11 / (1.0f + fexp(-v11));
            }
            const int m0 = m_base + mi * 16, m1 = m0 + 8;
            if (OUTT >= 1) {
                int kc = n >> 6;
                __half* Od = O;
                int ntiles = N >> 6;
                if (OUTT == 2) {
                    ntiles = 16;
                    if (kc >= 16) { Od = O2; kc -= 16; }
                }
                const int kk = n & 63;
                const size_t tb = ((size_t)mt * ntiles + kc) * TILE_ELEMS;
                const uint32_t o0 = sw128((m0 & 127) * 128 + kk * 2) >> 1;
                const uint32_t o1 = sw128((m1 & 127) * 128 + kk * 2) >> 1;
                *(uint32_t*)(Od + tb + o0) = pack_h2(v00, v01);
                *(uint32_t*)(Od + tb + o1) = pack_h2(v10, v11);
            } else {
                const size_t o0 = (size_t)m0 * N + n;
                const size_t o1 = (size_t)m1 * N + n;
                if (RES == 1) {
                    float2 r0 = *(const float2*)(resid + o0);
                    float2 r1 = *(const float2*)(resid + o1);
                    v00 += r0.x; v01 += r0.y; v10 += r1.x; v11 += r1.y;
                }
                *(float2*)(C + o0) = make_float2(v00, v01);
                *(float2*)(C + o1) = make_float2(v10, v11);
            }
        }
    }
}

// ---------------- tensor-core causal flash attention ---------------------
__global__ void __launch_bounds__(256, 2) flash_mma_kernel(
    const __half* __restrict__ Q, const __half* __restrict__ K,
    const __half* __restrict__ V, __half* __restrict__ Cc)
{
    extern __shared__ char smem[];
    const uint32_t sbase = smem_u32(smem);

    const int tid = threadIdx.x, lane = tid & 31, wq = tid >> 5;
    const int qt = 15 - blockIdx.x;           // big tiles first
    const int h = blockIdx.y, b = blockIdx.z;
    const int mtq = b * 16 + qt;
    const int KT = 2 * qt + 2;

    const uint32_t sQ = sbase;

    {
        const char* gQ = (const char*)(Q + ((size_t)mtq * 16 + h) * TILE_ELEMS);
        for (int j = tid; j < 1024; j += 256)
            cp16(sQ + j * 16, gQ + j * 16);
        asm volatile("cp.async.commit_group;" ::: "memory");
    }

    auto load_kv = [&](int kt) {
        const uint32_t st = sbase + 16384 + (uint32_t)(kt & 1) * 16384;
        const int mtk = b * 16 + (kt >> 1);
        const size_t toff = ((size_t)mtk * 16 + h) * TILE_ELEMS + (size_t)(kt & 1) * 4096;
        const char* gk = (const char*)(K + toff);
        const char* gv = (const char*)(V + toff);
        for (int j = tid; j < 512; j += 256) {
            cp16(st + j * 16,        gk + j * 16);
            cp16(st + 8192 + j * 16, gv + j * 16);
        }
        asm volatile("cp.async.commit_group;" ::: "memory");
    };
    load_kv(0);
    asm volatile("cp.async.wait_group 0;" ::: "memory");
    __syncthreads();

    const uint32_t xr = (uint32_t)((lane & 7) << 4);
    const uint32_t aRow = (uint32_t)((wq * 16 + (lane & 15)) * 128);
    const uint32_t kA = (uint32_t)((lane >> 4) * 16);
    uint32_t qf[4][4];
    #pragma unroll
    for (int ks = 0; ks < 4; ks++)
        ldsm4(qf[ks], sQ + aRow + (((uint32_t)(ks * 32) + kA) ^ xr));

    float o[8][4];
    #pragma unroll
    for (int nj = 0; nj < 8; nj++)
        #pragma unroll
        for (int q = 0; q < 4; q++) o[nj][q] = 0.f;
    float m0 = -1e30f, m1 = -1e30f, l0 = 0.f, l1 = 0.f;

    const uint32_t nbK = (uint32_t)(((lane >> 4) << 3) + (lane & 7));
    const uint32_t kB = (uint32_t)(((lane >> 3) & 1) * 16);
    const int vmi = lane >> 3, vri = lane & 7;

    const int row_lo = qt * 128 + wq * 16;

    for (int kt = 0; kt < KT; kt++) {
        if (kt + 1 < KT) {
            load_kv(kt + 1);
            asm volatile("cp.async.wait_group 1;" ::: "memory");
        } else {
            asm volatile("cp.async.wait_group 0;" ::: "memory");
        }
        __syncthreads();

        if (kt * 64 <= row_lo + 15) {
            const uint32_t st = sbase + 16384 + (uint32_t)(kt & 1) * 16384;
            const uint32_t sK = st, sV = st + 8192;

            float S[8][4];
            #pragma unroll
            for (int nj = 0; nj < 8; nj++)
                #pragma unroll
                for (int q = 0; q < 4; q++) S[nj][q] = 0.f;

            #pragma unroll
            for (int ks = 0; ks < 4; ks++) {
                const uint32_t kb = (uint32_t)(ks * 32) + kB;
                uint32_t bk[4][4];
                #pragma unroll
                for (int np = 0; np < 4; np++)
                    ldsm4(bk[np], sK + (nbK + np * 16) * 128 + (kb ^ xr));
                #pragma unroll
                for (int nj = 0; nj < 8; nj++)
                    mma_f16(S[nj], qf[ks], &bk[nj >> 1][(nj & 1) * 2]);
            }

            const int r0 = row_lo + (lane >> 2);
            const bool need_mask = (kt * 64 + 63) > row_lo;
            #pragma unroll
            for (int nj = 0; nj < 8; nj++)
                #pragma unroll
                for (int q = 0; q < 4; q++) S[nj][q] *= 0.125f;
            if (need_mask) {
                #pragma unroll
                for (int nj = 0; nj < 8; nj++)
                    #pragma unroll
                    for (int q = 0; q < 4; q++) {
                        const int kg = kt * 64 + nj * 8 + (lane & 3) * 2 + (q & 1);
                        const int qg = r0 + ((q >= 2) ? 8 : 0);
                        if (kg > qg) S[nj][q] = -1e30f;
                    }
            }

            float t0 = -1e30f, t1 = -1e30f;
            #pragma unroll
            for (int nj = 0; nj < 8; nj++) {
                t0 = fmaxf(t0, fmaxf(S[nj][0], S[nj][1]));
                t1 = fmaxf(t1, fmaxf(S[nj][2], S[nj][3]));
            }
            t0 = fmaxf(t0, __shfl_xor_sync(0xffffffffu, t0, 1));
            t0 = fmaxf(t0, __shfl_xor_sync(0xffffffffu, t0, 2));
            t1 = fmaxf(t1, __shfl_xor_sync(0xffffffffu, t1, 1));
            t1 = fmaxf(t1, __shfl_xor_sync(0xffffffffu, t1, 2));
            const float mn0 = fmaxf(m0, t0), mn1 = fmaxf(m1, t1);
            const float c0 = fexp(m0 - mn0), c1 = fexp(m1 - mn1);
            m0 = mn0; m1 = mn1;
            l0 *= c0; l1 *= c1;
            #pragma unroll
            for (int nj = 0; nj < 8; nj++) {
                o[nj][0] *= c0; o[nj][1] *= c0;
                o[nj][2] *= c1; o[nj][3] *= c1;
            }
            float ls0 = 0.f, ls1 = 0.f;
            #pragma unroll
            for (int nj = 0; nj < 8; nj++) {
                S[nj][0] = fexp(S[nj][0] - mn0); ls0 += S[nj][0];
                S[nj][1] = fexp(S[nj][1] - mn0); ls0 += S[nj][1];
                S[nj][2] = fexp(S[nj][2] - mn1); ls1 += S[nj][2];
                S[nj][3] = fexp(S[nj][3] - mn1); ls1 += S[nj][3];
            }
            l0 += ls0; l1 += ls1;

            #pragma unroll
            for (int kk = 0; kk < 4; kk++) {
                uint32_t ap[4];
                ap[0] = pack_h2(S[2*kk][0],   S[2*kk][1]);
                ap[1] = pack_h2(S[2*kk][2],   S[2*kk][3]);
                ap[2] = pack_h2(S[2*kk+1][0], S[2*kk+1][1]);
                ap[3] = pack_h2(S[2*kk+1][2], S[2*kk+1][3]);
                uint32_t vf[4][4];
                const uint32_t vrow = (uint32_t)(kk * 16 + (vmi & 1) * 8 + vri);
                #pragma unroll
                for (int g = 0; g < 4; g++) {
                    const uint32_t off = sw128(vrow * 128 + (uint32_t)(g * 16 + (vmi >> 1) * 8) * 2);
                    ldsm4t(vf[g], sV + off);
                }
                #pragma unroll
                for (int nj = 0; nj < 8; nj++)
                    mma_f16(o[nj], ap, &vf[nj >> 1][(nj & 1) * 2]);
            }
        }
        __syncthreads();
    }

    l0 += __shfl_xor_sync(0xffffffffu, l0, 1);
    l0 += __shfl_xor_sync(0xffffffffu, l0, 2);
    l1 += __shfl_xor_sync(0xffffffffu, l1, 1);
    l1 += __shfl_xor_sync(0xffffffffu, l1, 2);
    const float inv0 = 1.0f / l0, inv1 = 1.0f / l1;

    const size_t tb = ((size_t)mtq * 16 + h) * TILE_ELEMS;
    const int rl0 = wq * 16 + (lane >> 2), rl1 = rl0 + 8;
    #pragma unroll
    for (int nj = 0; nj < 8; nj++) {
        const int col = nj * 8 + (lane & 3) * 2;
        const uint32_t o0 = sw128(rl0 * 128 + col * 2) >> 1;
        const uint32_t o1 = sw128(rl1 * 128 + col * 2) >> 1;
        *(uint32_t*)(Cc + tb + o0) = pack_h2(o[nj][0] * inv0, o[nj][1] * inv0);
        *(uint32_t*)(Cc + tb + o1) = pack_h2(o[nj][2] * inv1, o[nj][3] * inv1);
    }
}

// ---------------- launch -------------------------------------------------
#define SYMADDR(p, s) cudaGetSymbolAddress((void**)&(p), s)

extern "C" void kernel_launch(void* const* d_in, const int* in_sizes, int n_in,
                              void* d_out, int out_size)
{
    const float* x         = (const float*)d_in[0];
    const float* rms_scale = (const float*)d_in[1];
    const float* in_proj_w = (const float*)d_in[2];
    const float* in_proj_b = (const float*)d_in[3];
    const float* out_proj_w= (const float*)d_in[4];
    const float* out_proj_b= (const float*)d_in[5];
    const float* w1        = (const float*)d_in[6];
    const float* b1        = (const float*)d_in[7];
    const float* w2        = (const float*)d_in[8];
    const float* b2        = (const float*)d_in[9];
    float* out = (float*)d_out;

    float *p_y;
    __half *xr, *xn, *q, *k, *v, *ctx, *yn, *hh;
    __half *wqkv, *wo, *w1h, *w2h;
    SYMADDR(p_y, g_y);
    SYMADDR(xr, t_xr);   SYMADDR(xn, t_xn);
    SYMADDR(q, t_q);     SYMADDR(k, t_k);    SYMADDR(v, t_v);
    SYMADDR(ctx, t_ctx); SYMADDR(yn, t_yn);  SYMADDR(hh, t_h);
    SYMADDR(wqkv, t_wqkv); SYMADDR(wo, t_wo);
    SYMADDR(w1h, t_w1);  SYMADDR(w2h, t_w2);
    __half* wv = wqkv + (size_t)2048 * DM;

    static bool inited = false;
    static cudaStream_t s2, s3;
    static cudaEvent_t evRoot, evW, evKW, evA, evV;
    if (!inited) {
        cudaStreamCreateWithFlags(&s2, cudaStreamNonBlocking);
        cudaStreamCreateWithFlags(&s3, cudaStreamNonBlocking);
        cudaEventCreateWithFlags(&evRoot, cudaEventDisableTiming);
        cudaEventCreateWithFlags(&evW,    cudaEventDisableTiming);
        cudaEventCreateWithFlags(&evKW,   cudaEventDisableTiming);
        cudaEventCreateWithFlags(&evA,    cudaEventDisableTiming);
        cudaEventCreateWithFlags(&evV,    cudaEventDisableTiming);
        cudaFuncSetAttribute(gemm_mma<0,0,0>, cudaFuncAttributeMaxDynamicSharedMemorySize, GEMM_SMEM);
        cudaFuncSetAttribute(gemm_mma<0,0,1>, cudaFuncAttributeMaxDynamicSharedMemorySize, GEMM_SMEM);
        cudaFuncSetAttribute(gemm_mma<0,0,2>, cudaFuncAttributeMaxDynamicSharedMemorySize, GEMM_SMEM);
        cudaFuncSetAttribute(gemm_mma<1,0,1>, cudaFuncAttributeMaxDynamicSharedMemorySize, GEMM_SMEM);
        cudaFuncSetAttribute(gemm_mma<0,1,0>, cudaFuncAttributeMaxDynamicSharedMemorySize, GEMM_SMEM);
        cudaFuncSetAttribute(flash_mma_kernel, cudaFuncAttributeMaxDynamicSharedMemorySize, ATTN_SMEM);
        inited = true;
    }

    // fork point
    cudaEventRecord(evRoot, 0);
    cudaStreamWaitEvent(s2, evRoot, 0);
    cudaStreamWaitEvent(s3, evRoot, 0);

    // s2: weight conversions not needed until step 4+
    conv_tiled_kernel<<<dim3(16, 8),  256, 0, s2>>>(out_proj_w, DM, wo);
    conv_tiled_kernel<<<dim3(16, 32), 256, 0, s2>>>(w1,         DM, w1h);
    conv_tiled_kernel<<<dim3(64, 8),  256, 0, s2>>>(w2,         FF, w2h);
    cudaEventRecord(evW, s2);

    // s3: qkv weight conversion, parallel to rms_rope
    conv_tiled_kernel<<<dim3(16, 24), 256, 0, s3>>>(in_proj_w, DM, wqkv);
    cudaEventRecord(evKW, s3);

    // main: xn = rmsnorm(x); xr = rope(xn)
    rms_rope_kernel<<<MROWS, 256>>>(x, rms_scale, xn, xr);
    cudaEventRecord(evA, 0);

    // s3: v = xn @ Wv^T  (after rms_rope; parallel to QK GEMM on main)
    cudaStreamWaitEvent(s3, evA, 0);
    gemm_mma<0,0,1><<<dim3(8, 32), 256, GEMM_SMEM, s3>>>(
        xn, wv, in_proj_b + 2 * DM, nullptr, nullptr, v, nullptr, DM, DM);
    cudaEventRecord(evV, s3);

    // main: [q|k] = xr @ [Wq;Wk]^T + b (needs wqkv conversion)
    cudaStreamWaitEvent(0, evKW, 0);
    gemm_mma<0,0,2><<<dim3(16, 32), 256, GEMM_SMEM>>>(
        xr, wqkv, in_proj_b, nullptr, nullptr, q, k, 2 * DM, DM);

    // join: attention needs q,k (main) and v (s3)
    cudaStreamWaitEvent(0, evV, 0);
    flash_mma_kernel<<<dim3(16, NH, BATCH), 256, ATTN_SMEM>>>(q, k, v, ctx);

    // join: Wo/W1/W2 conversions
    cudaStreamWaitEvent(0, evW, 0);

    // y = ctx @ Wo^T + b
    gemm_mma<0,0,0><<<dim3(8, 32), 256, GEMM_SMEM>>>(
        ctx, wo, out_proj_b, nullptr, p_y, nullptr, nullptr, DM, DM);

    // yn = rmsnorm(y)
    rms_rope_kernel<<<MROWS, 256>>>(p_y, rms_scale, yn, nullptr);

    // h = silu(yn @ w1^T + b1) -> tiled fp16
    gemm_mma<1,0,1><<<dim3(32, 32), 256, GEMM_SMEM>>>(
        yn, w1h, b1, nullptr, nullptr, hh, nullptr, FF, DM);

    // out = y + (h @ w2^T + b2)
    gemm_mma<0,1,0><<<dim3(8, 32), 256, GEMM_SMEM>>>(
        hh, w2h, b2, p_y, out, nullptr, nullptr, DM, FF);
}